// round 1
// baseline (speedup 1.0000x reference)
#include <cuda_runtime.h>
#include <cstdint>

// Problem constants (fixed by the reference).
#define NB 8
#define NA 65536
#define NC 80
#define NM 32
#define IMG_WH 512.0f
#define TPB 256

// ---------------------------------------------------------------------------
// Scratch (no allocations allowed -> __device__ globals)
// ---------------------------------------------------------------------------
__device__ float    g_cls[NB];
__device__ float    g_reg[NB];
__device__ float    g_loc[NB];
__device__ int      g_np[NB];
__device__ unsigned g_used[NB];
__device__ unsigned g_posmask[NB * NA / 32];

// ---------------------------------------------------------------------------
__global__ void init_kernel() {
    int t = threadIdx.x;
    if (t < NB) {
        g_cls[t] = 0.f; g_reg[t] = 0.f; g_loc[t] = 0.f;
        g_np[t] = 0;    g_used[t] = 0u;
    }
}

__device__ __forceinline__ float warp_sum_f(float v) {
#pragma unroll
    for (int o = 16; o > 0; o >>= 1) v += __shfl_down_sync(0xffffffffu, v, o);
    return v;
}
__device__ __forceinline__ int warp_sum_i(int v) {
#pragma unroll
    for (int o = 16; o > 0; o >>= 1) v += __shfl_down_sync(0xffffffffu, v, o);
    return v;
}

// ---------------------------------------------------------------------------
// Pass 1: iou/argmax, pos/neg, focal cls loss, smooth-L1 reg loss,
//         pos bitmask + gt_used mask.
// ---------------------------------------------------------------------------
__global__ __launch_bounds__(TPB)
void pass1_kernel(const float* __restrict__ cls,
                  const float* __restrict__ reg,
                  const float* __restrict__ anc,
                  const float* __restrict__ ann) {
    const int b = blockIdx.y;
    const int i = blockIdx.x * TPB + threadIdx.x;   // anchor index

    __shared__ float4  sbox[NM];
    __shared__ float   slbl[NM];
    __shared__ float   sarea[NM];
    __shared__ unsigned s_used;
    __shared__ float   sc[TPB / 32], sr[TPB / 32];
    __shared__ int     sn[TPB / 32];

    if (threadIdx.x < NM) {
        const float* a5 = ann + ((size_t)b * NM + threadIdx.x) * 5;
        float4 bx = make_float4(a5[0], a5[1], a5[2], a5[3]);
        sbox[threadIdx.x]  = bx;
        slbl[threadIdx.x]  = a5[4];
        sarea[threadIdx.x] = (bx.z - bx.x) * (bx.w - bx.y);
    }
    if (threadIdx.x == 0) s_used = 0u;
    __syncthreads();

    const float4 an = __ldg(((const float4*)anc) + i);
    const float aw = an.z - an.x;
    const float ah = an.w - an.y;
    const float area_a = aw * ah;

    // iou max / argmax (first occurrence of max, like jnp.argmax)
    float best = -1e30f;
    int   arg  = 0;
#pragma unroll
    for (int m = 0; m < NM; m++) {
        float4 bx = sbox[m];
        float iw = fmaxf(fminf(an.z, bx.z) - fmaxf(an.x, bx.x), 0.f);
        float ih = fmaxf(fminf(an.w, bx.w) - fmaxf(an.y, bx.y), 0.f);
        float inter = iw * ih;
        float iou = inter / fmaxf(area_a + sarea[m] - inter, 1e-8f);
        if (slbl[m] == -1.0f) iou = -1.0f;
        if (iou > best) { best = iou; arg = m; }
    }
    const bool pos = best >= 0.5f;
    const bool neg = best < 0.4f;

    // persist pos bits for pass2
    unsigned bal = __ballot_sync(0xffffffffu, pos);
    if ((threadIdx.x & 31) == 0)
        g_posmask[((size_t)b * NA + i) >> 5] = bal;

    float cls_acc = 0.f;
    float reg_acc = 0.f;

    if (pos | neg) {
        const int lbl = pos ? (int)slbl[arg] : -1;
        const float4* row = (const float4*)(cls + ((size_t)b * NA + i) * NC);
        float p_lbl = 0.f;
#pragma unroll
        for (int j = 0; j < NC / 4; j++) {
            float4 v = __ldg(row + j);
            float pv[4] = {v.x, v.y, v.z, v.w};
#pragma unroll
            for (int k = 0; k < 4; k++) {
                float p = fminf(fmaxf(pv[k], 1e-4f), 1.f - 1e-4f);
                // target==0 branch: 0.75 * p^2 * (-log(1-p))
                cls_acc += 0.75f * p * p * (-logf(1.f - p));
                if (4 * j + k == lbl) p_lbl = p;
            }
        }
        if (pos) {
            // replace the label-class term by the target==1 branch
            cls_acc -= 0.75f * p_lbl * p_lbl * (-logf(1.f - p_lbl));
            cls_acc += 0.25f * (1.f - p_lbl) * (1.f - p_lbl) * (-logf(p_lbl));
        }
    }

    if (pos) {
        float4 bx = sbox[arg];
        float gwr = bx.z - bx.x;
        float ghr = bx.w - bx.y;
        float gcx = bx.x + 0.5f * gwr;
        float gcy = bx.y + 0.5f * ghr;
        float gw = fmaxf(gwr, 1.f);
        float gh = fmaxf(ghr, 1.f);
        float acx = an.x + 0.5f * aw;
        float acy = an.y + 0.5f * ah;
        float t0 = ((gcx - acx) / aw) / 0.1f;
        float t1 = ((gcy - acy) / ah) / 0.1f;
        float t2 = logf(gw / aw) / 0.2f;
        float t3 = logf(gh / ah) / 0.2f;
        float4 rp = __ldg(((const float4*)reg) + (size_t)b * NA + i);
        float d0 = fabsf(t0 - rp.x);
        float d1 = fabsf(t1 - rp.y);
        float d2 = fabsf(t2 - rp.z);
        float d3 = fabsf(t3 - rp.w);
        const float th = 1.0f / 9.0f;
        reg_acc += (d0 <= th) ? 4.5f * d0 * d0 : d0 - 0.5f / 9.0f;
        reg_acc += (d1 <= th) ? 4.5f * d1 * d1 : d1 - 0.5f / 9.0f;
        reg_acc += (d2 <= th) ? 4.5f * d2 * d2 : d2 - 0.5f / 9.0f;
        reg_acc += (d3 <= th) ? 4.5f * d3 * d3 : d3 - 0.5f / 9.0f;
        atomicOr(&s_used, 1u << arg);
    }

    // block reduction
    float wc = warp_sum_f(cls_acc);
    float wr = warp_sum_f(reg_acc);
    int   wn = warp_sum_i(pos ? 1 : 0);
    int w = threadIdx.x >> 5, lane = threadIdx.x & 31;
    if (lane == 0) { sc[w] = wc; sr[w] = wr; sn[w] = wn; }
    __syncthreads();
    if (threadIdx.x == 0) {
        float tc = 0.f, tr = 0.f; int tn = 0;
#pragma unroll
        for (int k = 0; k < TPB / 32; k++) { tc += sc[k]; tr += sr[k]; tn += sn[k]; }
        if (tc != 0.f) atomicAdd(&g_cls[b], tc);
        if (tr != 0.f) atomicAdd(&g_reg[b], tr);
        if (tn)        atomicAdd(&g_np[b], tn);
        if (s_used)    atomicOr(&g_used[b], s_used);
    }
}

// ---------------------------------------------------------------------------
// Pass 2: loc loss (needs gt_used complete). Only pos anchors do real work.
// ---------------------------------------------------------------------------
__global__ __launch_bounds__(TPB)
void pass2_kernel(const float* __restrict__ reg,
                  const float* __restrict__ loc,
                  const float* __restrict__ anc,
                  const float* __restrict__ ann) {
    const int b = blockIdx.y;
    const int i = blockIdx.x * TPB + threadIdx.x;

    __shared__ float4 sbox[NM];
    __shared__ float  sarea[NM];
    __shared__ int    suse[NM];
    __shared__ float  sl[TPB / 32];

    if (threadIdx.x < NM) {
        const float* a5 = ann + ((size_t)b * NM + threadIdx.x) * 5;
        float4 bx = make_float4(a5[0], a5[1], a5[2], a5[3]);
        sbox[threadIdx.x]  = bx;
        sarea[threadIdx.x] = (bx.z - bx.x) * (bx.w - bx.y);
        unsigned um = g_used[b];
        suse[threadIdx.x] = ((um >> threadIdx.x) & 1u) && (a5[4] != -1.0f);
    }
    __syncthreads();

    unsigned pm = g_posmask[((size_t)b * NA + i) >> 5];
    bool pos = (pm >> (i & 31)) & 1u;

    float loc_acc = 0.f;
    if (pos) {
        float4 an = __ldg(((const float4*)anc) + i);
        float aw = an.z - an.x;
        float ah = an.w - an.y;
        float acx = an.x + 0.5f * aw;
        float acy = an.y + 0.5f * ah;
        float4 rp = __ldg(((const float4*)reg) + (size_t)b * NA + i);
        float dx = rp.x * 0.1f, dy = rp.y * 0.1f;
        float dw = rp.z * 0.2f, dh = rp.w * 0.2f;
        float pcx = acx + dx * aw, pcy = acy + dy * ah;
        float pw = expf(dw) * aw, ph = expf(dh) * ah;
        float sx1 = fminf(fmaxf(pcx - 0.5f * pw, 0.f), IMG_WH);
        float sy1 = fminf(fmaxf(pcy - 0.5f * ph, 0.f), IMG_WH);
        float sx2 = fminf(fmaxf(pcx + 0.5f * pw, 0.f), IMG_WH);
        float sy2 = fminf(fmaxf(pcy + 0.5f * ph, 0.f), IMG_WH);
        float area_s = (sx2 - sx1) * (sy2 - sy1);

        float best = -1e9f;   // matches the -1000000000.0 fill
#pragma unroll
        for (int m = 0; m < NM; m++) {
            if (suse[m]) {
                float4 bx = sbox[m];
                float iw = fmaxf(fminf(sx2, bx.z) - fmaxf(sx1, bx.x), 0.f);
                float ih = fmaxf(fminf(sy2, bx.w) - fmaxf(sy1, bx.y), 0.f);
                float inter = iw * ih;
                float iou = inter / fmaxf(area_s + sarea[m] - inter, 1e-8f);
                best = fmaxf(best, iou);
            }
        }
        float lp = __ldg(loc + (size_t)b * NA + i);
        float ls = fminf(fmaxf(1.f - fabsf(lp - best), 1e-4f), 1.f - 1e-4f);
        loc_acc = -logf(ls);
    }

    float wl = warp_sum_f(loc_acc);
    int w = threadIdx.x >> 5, lane = threadIdx.x & 31;
    if (lane == 0) sl[w] = wl;
    __syncthreads();
    if (threadIdx.x == 0) {
        float tl = 0.f;
#pragma unroll
        for (int k = 0; k < TPB / 32; k++) tl += sl[k];
        if (tl != 0.f) atomicAdd(&g_loc[b], tl);
    }
}

// ---------------------------------------------------------------------------
// Finalize: per-image normalization + gating + mean over batch.
// ---------------------------------------------------------------------------
__global__ void finalize_kernel(const float* __restrict__ ann, float* __restrict__ out) {
    int b = threadIdx.x;
    float c = 0.f, r = 0.f, l = 0.f;
    if (b < NB) {
        bool has_gt = false;
        for (int m = 0; m < NM; m++)
            if (ann[((size_t)b * NM + m) * 5 + 4] != -1.0f) has_gt = true;
        float np = (float)g_np[b];
        bool ok = has_gt && (np > 0.f);
        c = has_gt ? g_cls[b] / fmaxf(np, 1.f)        : 0.f;
        r = ok     ? g_reg[b] / fmaxf(np * 4.f, 1.f)  : 0.f;
        l = ok     ? g_loc[b] / fmaxf(np, 1.f)        : 0.f;
    }
#pragma unroll
    for (int o = 16; o > 0; o >>= 1) {
        c += __shfl_down_sync(0xffffffffu, c, o);
        r += __shfl_down_sync(0xffffffffu, r, o);
        l += __shfl_down_sync(0xffffffffu, l, o);
    }
    if (threadIdx.x == 0) {
        out[0] = c / (float)NB;
        out[1] = r / (float)NB;
        out[2] = l / (float)NB;
    }
}

// ---------------------------------------------------------------------------
extern "C" void kernel_launch(void* const* d_in, const int* in_sizes, int n_in,
                              void* d_out, int out_size) {
    const float* cls = (const float*)d_in[0];  // (B,A,C)
    const float* reg = (const float*)d_in[1];  // (B,A,4)
    const float* loc = (const float*)d_in[2];  // (B,A,1)
    const float* anc = (const float*)d_in[3];  // (1,A,4)
    const float* ann = (const float*)d_in[4];  // (B,M,5)
    float* out = (float*)d_out;                // 3 floats

    init_kernel<<<1, 32>>>();
    dim3 grid(NA / TPB, NB);
    pass1_kernel<<<grid, TPB>>>(cls, reg, anc, ann);
    pass2_kernel<<<grid, TPB>>>(reg, loc, anc, ann);
    finalize_kernel<<<1, 32>>>(ann, out);
}

// round 2
// speedup vs baseline: 1.1594x; 1.1594x over previous
#include <cuda_runtime.h>
#include <cstdint>

#define NB 8
#define NA 65536
#define NC 80
#define NM 32
#define IMG_WH 512.0f
#define TPB 256
#define F4R 20                     // float4 per classification row (80 floats)
#define FLAG_BLOCKS (NA / TPB)     // 256 blocks per image
#define CLS_BLOCKS 512             // x-blocks per image for cls streaming
#define P2_BLOCKS 256

// ---------------------------------------------------------------------------
// Scratch (__device__ globals; no atomic-accumulators -> no init kernel)
// ---------------------------------------------------------------------------
__device__ int8_t   g_flags[NB * NA];              // label if pos, -1 neg, -2 skip
__device__ unsigned g_posmask[NB * NA / 32];
__device__ float    g_part_reg[NB * FLAG_BLOCKS];
__device__ int      g_part_np [NB * FLAG_BLOCKS];
__device__ unsigned g_part_used[NB * FLAG_BLOCKS];
__device__ float    g_part_cls[NB * CLS_BLOCKS];
__device__ float    g_part_loc[NB * P2_BLOCKS];
__device__ int      g_ticket = 0;

__device__ __forceinline__ float warp_sum_f(float v) {
#pragma unroll
    for (int o = 16; o > 0; o >>= 1) v += __shfl_down_sync(0xffffffffu, v, o);
    return v;
}
__device__ __forceinline__ int warp_sum_i(int v) {
#pragma unroll
    for (int o = 16; o > 0; o >>= 1) v += __shfl_down_sync(0xffffffffu, v, o);
    return v;
}

// ---------------------------------------------------------------------------
// Kernel 1: per-anchor flags, reg loss, posmask, per-block partials.
// ---------------------------------------------------------------------------
__global__ __launch_bounds__(TPB)
void flags_kernel(const float* __restrict__ reg,
                  const float* __restrict__ anc,
                  const float* __restrict__ ann) {
    const int b = blockIdx.y;
    const int i = blockIdx.x * TPB + threadIdx.x;

    __shared__ float4   sbox[NM];
    __shared__ float    slbl[NM];
    __shared__ float    sarea[NM];
    __shared__ unsigned s_used;
    __shared__ float    sr[TPB / 32];
    __shared__ int      sn[TPB / 32];

    if (threadIdx.x < NM) {
        const float* a5 = ann + ((size_t)b * NM + threadIdx.x) * 5;
        float4 bx = make_float4(a5[0], a5[1], a5[2], a5[3]);
        sbox[threadIdx.x]  = bx;
        slbl[threadIdx.x]  = a5[4];
        sarea[threadIdx.x] = (bx.z - bx.x) * (bx.w - bx.y);
    }
    if (threadIdx.x == 0) s_used = 0u;
    __syncthreads();

    const float4 an = __ldg(((const float4*)anc) + i);
    const float aw = an.z - an.x;
    const float ah = an.w - an.y;
    const float area_a = aw * ah;

    float best = -1e30f;
    int   arg  = 0;
#pragma unroll
    for (int m = 0; m < NM; m++) {
        float4 bx = sbox[m];
        float iw = fmaxf(fminf(an.z, bx.z) - fmaxf(an.x, bx.x), 0.f);
        float ih = fmaxf(fminf(an.w, bx.w) - fmaxf(an.y, bx.y), 0.f);
        float inter = iw * ih;
        float iou = inter / fmaxf(area_a + sarea[m] - inter, 1e-8f);
        if (slbl[m] == -1.0f) iou = -1.0f;
        if (iou > best) { best = iou; arg = m; }   // first-max (jnp.argmax)
    }
    const bool pos = best >= 0.5f;
    const bool neg = best < 0.4f;

    int8_t flag = pos ? (int8_t)slbl[arg] : (neg ? (int8_t)-1 : (int8_t)-2);
    g_flags[(size_t)b * NA + i] = flag;

    unsigned bal = __ballot_sync(0xffffffffu, pos);
    if ((threadIdx.x & 31) == 0)
        g_posmask[((size_t)b * NA + i) >> 5] = bal;

    float reg_acc = 0.f;
    if (pos) {
        float4 bx = sbox[arg];
        float gwr = bx.z - bx.x;
        float ghr = bx.w - bx.y;
        float gcx = bx.x + 0.5f * gwr;
        float gcy = bx.y + 0.5f * ghr;
        float gw = fmaxf(gwr, 1.f);
        float gh = fmaxf(ghr, 1.f);
        float acx = an.x + 0.5f * aw;
        float acy = an.y + 0.5f * ah;
        float t0 = ((gcx - acx) / aw) / 0.1f;
        float t1 = ((gcy - acy) / ah) / 0.1f;
        float t2 = __logf(gw / aw) / 0.2f;
        float t3 = __logf(gh / ah) / 0.2f;
        float4 rp = __ldg(((const float4*)reg) + (size_t)b * NA + i);
        float d0 = fabsf(t0 - rp.x);
        float d1 = fabsf(t1 - rp.y);
        float d2 = fabsf(t2 - rp.z);
        float d3 = fabsf(t3 - rp.w);
        const float th = 1.0f / 9.0f;
        reg_acc += (d0 <= th) ? 4.5f * d0 * d0 : d0 - 0.5f / 9.0f;
        reg_acc += (d1 <= th) ? 4.5f * d1 * d1 : d1 - 0.5f / 9.0f;
        reg_acc += (d2 <= th) ? 4.5f * d2 * d2 : d2 - 0.5f / 9.0f;
        reg_acc += (d3 <= th) ? 4.5f * d3 * d3 : d3 - 0.5f / 9.0f;
        atomicOr(&s_used, 1u << arg);
    }

    float wr = warp_sum_f(reg_acc);
    int   wn = warp_sum_i(pos ? 1 : 0);
    int w = threadIdx.x >> 5, lane = threadIdx.x & 31;
    if (lane == 0) { sr[w] = wr; sn[w] = wn; }
    __syncthreads();
    if (threadIdx.x == 0) {
        float tr = 0.f; int tn = 0;
#pragma unroll
        for (int k = 0; k < TPB / 32; k++) { tr += sr[k]; tn += sn[k]; }
        int pidx = b * FLAG_BLOCKS + blockIdx.x;
        g_part_reg[pidx]  = tr;
        g_part_np [pidx]  = tn;
        g_part_used[pidx] = s_used;
    }
}

// ---------------------------------------------------------------------------
// Kernel 2: coalesced streaming focal-BCE over classifications.
// ---------------------------------------------------------------------------
__global__ __launch_bounds__(TPB)
void cls_kernel(const float* __restrict__ cls) {
    const int b = blockIdx.y;
    const float4* base = (const float4*)(cls + (size_t)b * NA * NC);
    const int8_t* flags = g_flags + (size_t)b * NA;

    float acc = 0.f;
    int idx = blockIdx.x * TPB + threadIdx.x;
#pragma unroll
    for (int it = 0; it < (NA * F4R) / (CLS_BLOCKS * TPB); it++) {  // 10 iters
        unsigned a = (unsigned)idx / F4R;
        int j = idx - (int)a * F4R;
        int flag = flags[a];
        if (flag != -2) {
            float4 v = __ldg(base + idx);
            float pv[4] = {v.x, v.y, v.z, v.w};
            int c0 = 4 * j;
#pragma unroll
            for (int k = 0; k < 4; k++) {
                float p = fminf(fmaxf(pv[k], 1e-4f), 1.f - 1e-4f);
                if (flag == c0 + k)
                    acc += 0.25f * (1.f - p) * (1.f - p) * (-__logf(p));
                else
                    acc += 0.75f * p * p * (-__logf(1.f - p));
            }
        }
        idx += CLS_BLOCKS * TPB;
    }

    __shared__ float sc[TPB / 32];
    float wc = warp_sum_f(acc);
    int w = threadIdx.x >> 5, lane = threadIdx.x & 31;
    if (lane == 0) sc[w] = wc;
    __syncthreads();
    if (threadIdx.x == 0) {
        float tc = 0.f;
#pragma unroll
        for (int k = 0; k < TPB / 32; k++) tc += sc[k];
        g_part_cls[b * CLS_BLOCKS + blockIdx.x] = tc;
    }
}

// ---------------------------------------------------------------------------
// Kernel 3: loc loss + ticket-based finalize in the last block.
// ---------------------------------------------------------------------------
__global__ __launch_bounds__(TPB)
void pass2_kernel(const float* __restrict__ reg,
                  const float* __restrict__ loc,
                  const float* __restrict__ anc,
                  const float* __restrict__ ann,
                  float* __restrict__ out) {
    const int b = blockIdx.y;
    const int i = blockIdx.x * TPB + threadIdx.x;

    __shared__ float4   sbox[NM];
    __shared__ float    sarea[NM];
    __shared__ unsigned s_used;
    __shared__ unsigned s_mask;
    __shared__ float    sl[TPB / 32];

    if (threadIdx.x == 0) s_used = 0u;
    __syncthreads();

    // image-level gt_used mask = OR of flag-kernel partials (FLAG_BLOCKS==TPB)
    {
        unsigned um = g_part_used[b * FLAG_BLOCKS + threadIdx.x];
#pragma unroll
        for (int o = 16; o > 0; o >>= 1) um |= __shfl_xor_sync(0xffffffffu, um, o);
        if ((threadIdx.x & 31) == 0) atomicOr(&s_used, um);
    }
    if (threadIdx.x < NM) {
        const float* a5 = ann + ((size_t)b * NM + threadIdx.x) * 5;
        float4 bx = make_float4(a5[0], a5[1], a5[2], a5[3]);
        sbox[threadIdx.x]  = bx;
        sarea[threadIdx.x] = (bx.z - bx.x) * (bx.w - bx.y);
    }
    __syncthreads();
    if (threadIdx.x == 0) {
        unsigned m = s_used;
        for (int k = 0; k < NM; k++) {
            const float* a5 = ann + ((size_t)b * NM + k) * 5;
            if (a5[4] == -1.0f) m &= ~(1u << k);
        }
        s_mask = m;
    }
    __syncthreads();
    const unsigned mask = s_mask;

    unsigned pm = g_posmask[((size_t)b * NA + i) >> 5];
    bool pos = (pm >> (i & 31)) & 1u;

    float loc_acc = 0.f;
    if (pos) {
        float4 an = __ldg(((const float4*)anc) + i);
        float aw = an.z - an.x;
        float ah = an.w - an.y;
        float acx = an.x + 0.5f * aw;
        float acy = an.y + 0.5f * ah;
        float4 rp = __ldg(((const float4*)reg) + (size_t)b * NA + i);
        float pcx = acx + rp.x * 0.1f * aw, pcy = acy + rp.y * 0.1f * ah;
        float pw = __expf(rp.z * 0.2f) * aw, ph = __expf(rp.w * 0.2f) * ah;
        float sx1 = fminf(fmaxf(pcx - 0.5f * pw, 0.f), IMG_WH);
        float sy1 = fminf(fmaxf(pcy - 0.5f * ph, 0.f), IMG_WH);
        float sx2 = fminf(fmaxf(pcx + 0.5f * pw, 0.f), IMG_WH);
        float sy2 = fminf(fmaxf(pcy + 0.5f * ph, 0.f), IMG_WH);
        float area_s = (sx2 - sx1) * (sy2 - sy1);

        float best = -1e9f;
#pragma unroll
        for (int m = 0; m < NM; m++) {
            if ((mask >> m) & 1u) {
                float4 bx = sbox[m];
                float iw = fmaxf(fminf(sx2, bx.z) - fmaxf(sx1, bx.x), 0.f);
                float ih = fmaxf(fminf(sy2, bx.w) - fmaxf(sy1, bx.y), 0.f);
                float inter = iw * ih;
                best = fmaxf(best, inter / fmaxf(area_s + sarea[m] - inter, 1e-8f));
            }
        }
        float lp = __ldg(loc + (size_t)b * NA + i);
        float ls = fminf(fmaxf(1.f - fabsf(lp - best), 1e-4f), 1.f - 1e-4f);
        loc_acc = -__logf(ls);
    }

    float wl = warp_sum_f(loc_acc);
    int w = threadIdx.x >> 5, lane = threadIdx.x & 31;
    if (lane == 0) sl[w] = wl;
    __syncthreads();
    if (threadIdx.x == 0) {
        float tl = 0.f;
#pragma unroll
        for (int k = 0; k < TPB / 32; k++) tl += sl[k];
        g_part_loc[b * P2_BLOCKS + blockIdx.x] = tl;
        __threadfence();
    }
    __syncthreads();

    // ---- ticket: last block finalizes ----
    __shared__ int s_last;
    if (threadIdx.x == 0) {
        int t = atomicAdd(&g_ticket, 1);
        s_last = (t == (int)(gridDim.x * gridDim.y) - 1);
    }
    __syncthreads();
    if (!s_last) return;

    // 8 warps: warp w handles image w
    __shared__ float f_c[NB], f_r[NB], f_l[NB];
    {
        int wi = threadIdx.x >> 5;
        int ln = threadIdx.x & 31;
        if (wi < NB) {
            float cs = 0.f;
#pragma unroll
            for (int k = 0; k < CLS_BLOCKS / 32; k++)
                cs += g_part_cls[wi * CLS_BLOCKS + k * 32 + ln];
            float rs = 0.f, lsum = 0.f; int np = 0;
#pragma unroll
            for (int k = 0; k < FLAG_BLOCKS / 32; k++) {
                int p = wi * FLAG_BLOCKS + k * 32 + ln;
                rs   += g_part_reg[p];
                np   += g_part_np[p];
                lsum += g_part_loc[p];
            }
            cs = warp_sum_f(cs); rs = warp_sum_f(rs);
            lsum = warp_sum_f(lsum); np = warp_sum_i(np);
            bool v = (ln < NM) && (ann[((size_t)wi * NM + ln) * 5 + 4] != -1.0f);
            bool has_gt = __ballot_sync(0xffffffffu, v) != 0u;
            if (ln == 0) {
                float fnp = (float)np;
                bool ok = has_gt && (np > 0);
                f_c[wi] = has_gt ? cs / fmaxf(fnp, 1.f)          : 0.f;
                f_r[wi] = ok     ? rs / fmaxf(fnp * 4.f, 1.f)    : 0.f;
                f_l[wi] = ok     ? lsum / fmaxf(fnp, 1.f)        : 0.f;
            }
        }
    }
    __syncthreads();
    if (threadIdx.x == 0) {
        float c = 0.f, r = 0.f, l = 0.f;
#pragma unroll
        for (int k = 0; k < NB; k++) { c += f_c[k]; r += f_r[k]; l += f_l[k]; }
        out[0] = c / (float)NB;
        out[1] = r / (float)NB;
        out[2] = l / (float)NB;
        g_ticket = 0;   // reset for graph replay determinism
    }
}

// ---------------------------------------------------------------------------
extern "C" void kernel_launch(void* const* d_in, const int* in_sizes, int n_in,
                              void* d_out, int out_size) {
    const float* cls = (const float*)d_in[0];  // (B,A,C)
    const float* reg = (const float*)d_in[1];  // (B,A,4)
    const float* loc = (const float*)d_in[2];  // (B,A,1)
    const float* anc = (const float*)d_in[3];  // (1,A,4)
    const float* ann = (const float*)d_in[4];  // (B,M,5)
    float* out = (float*)d_out;

    flags_kernel<<<dim3(FLAG_BLOCKS, NB), TPB>>>(reg, anc, ann);
    cls_kernel<<<dim3(CLS_BLOCKS, NB), TPB>>>(cls);
    pass2_kernel<<<dim3(P2_BLOCKS, NB), TPB>>>(reg, loc, anc, ann, out);
}

// round 3
// speedup vs baseline: 1.1887x; 1.0253x over previous
#include <cuda_runtime.h>
#include <cstdint>

#define NB 8
#define NA 65536
#define NC 80
#define NM 32
#define IMG_WH 512.0f
#define TPB 256
#define F4R 20                     // float4 per classification row
#define FLAG_BLOCKS (NA / TPB)     // 256 blocks/image
#define CLS_BLOCKS 640             // x-blocks/image for cls streaming
#define P2_BLOCKS 256
#define NEG_LN2_075 (-0.5198603854199589f)   // -0.75*ln(2)

// ---------------------------------------------------------------------------
// Scratch
// ---------------------------------------------------------------------------
__device__ int8_t   g_flags[NB * NA];          // label if pos, -1 neg, -2 ignore
__device__ unsigned g_posmask[NB * NA / 32];
__device__ float    g_part_reg[NB * FLAG_BLOCKS];
__device__ int      g_part_np [NB * FLAG_BLOCKS];
__device__ unsigned g_part_used[NB * FLAG_BLOCKS];
__device__ float    g_part_cls[NB * CLS_BLOCKS];
__device__ float    g_part_loc[NB * P2_BLOCKS];
__device__ float    g_part_fix[NB * P2_BLOCKS];
__device__ int      g_ticket = 0;

__device__ __forceinline__ float warp_sum_f(float v) {
#pragma unroll
    for (int o = 16; o > 0; o >>= 1) v += __shfl_down_sync(0xffffffffu, v, o);
    return v;
}
__device__ __forceinline__ int warp_sum_i(int v) {
#pragma unroll
    for (int o = 16; o > 0; o >>= 1) v += __shfl_down_sync(0xffffffffu, v, o);
    return v;
}

// ---------------------------------------------------------------------------
// Kernel 1: flags (division-free), reg loss, posmask, partials.
// ---------------------------------------------------------------------------
__global__ __launch_bounds__(TPB)
void flags_kernel(const float* __restrict__ reg,
                  const float* __restrict__ anc,
                  const float* __restrict__ ann) {
    const int b = blockIdx.y;
    const int i = blockIdx.x * TPB + threadIdx.x;

    __shared__ float4   sbox[NM];
    __shared__ float    slbl[NM];
    __shared__ float    sarea_eff[NM];   // +1e30 for invalid boxes
    __shared__ unsigned s_used;
    __shared__ float    sr[TPB / 32];
    __shared__ int      sn[TPB / 32];

    if (threadIdx.x < NM) {
        const float* a5 = ann + ((size_t)b * NM + threadIdx.x) * 5;
        float4 bx = make_float4(a5[0], a5[1], a5[2], a5[3]);
        float lbl = a5[4];
        sbox[threadIdx.x] = bx;
        slbl[threadIdx.x] = lbl;
        sarea_eff[threadIdx.x] = (lbl == -1.0f) ? 1e30f
                               : (bx.z - bx.x) * (bx.w - bx.y);
    }
    if (threadIdx.x == 0) s_used = 0u;
    __syncthreads();

    const float4 an = __ldg(((const float4*)anc) + i);
    const float aw = an.z - an.x;
    const float ah = an.w - an.y;
    const float area_a = aw * ah;

    // Phase A: pos/neg flags without division or argmax.
    float maxPos = -1e30f;     // max(3*inter - (area_a+area_b))
    float maxNeg = -1e30f;     // max(3.5*inter - (area_a+area_b))
#pragma unroll
    for (int m = 0; m < NM; m++) {
        float4 bx = sbox[m];
        float iw = fmaxf(fminf(an.z, bx.z) - fmaxf(an.x, bx.x), 0.f);
        float ih = fmaxf(fminf(an.w, bx.w) - fmaxf(an.y, bx.y), 0.f);
        float inter = iw * ih;
        float sab = area_a + sarea_eff[m];
        maxPos = fmaxf(maxPos, fmaf(3.0f, inter, -sab));
        maxNeg = fmaxf(maxNeg, fmaf(3.5f, inter, -sab));
    }
    const bool pos = maxPos >= 0.f;
    const bool neg = maxNeg < 0.f;

    unsigned bal = __ballot_sync(0xffffffffu, pos);
    if ((threadIdx.x & 31) == 0)
        g_posmask[((size_t)b * NA + i) >> 5] = bal;

    float reg_acc = 0.f;
    int8_t flag = neg ? (int8_t)-1 : (int8_t)-2;

    if (pos) {
        // Phase B: division-free first-max argmax (rare path).
        float bi = -1.f, bd = 1.f;   // best iou as fraction bi/bd
        int arg = 0;
#pragma unroll
        for (int m = 0; m < NM; m++) {
            float4 bx = sbox[m];
            float iw = fmaxf(fminf(an.z, bx.z) - fmaxf(an.x, bx.x), 0.f);
            float ih = fmaxf(fminf(an.w, bx.w) - fmaxf(an.y, bx.y), 0.f);
            float inter = iw * ih;
            float area_b = (bx.z - bx.x) * (bx.w - bx.y);
            float den = area_a + area_b - inter;
            bool invalid = (slbl[m] == -1.0f);
            float im = invalid ? -1.f : inter;
            float dm = invalid ?  1.f : den;
            if (im * bd > bi * dm) { bi = im; bd = dm; arg = m; }
        }
        flag = (int8_t)slbl[arg];

        float4 bx = sbox[arg];
        float gwr = bx.z - bx.x;
        float ghr = bx.w - bx.y;
        float gcx = bx.x + 0.5f * gwr;
        float gcy = bx.y + 0.5f * ghr;
        float gw = fmaxf(gwr, 1.f);
        float gh = fmaxf(ghr, 1.f);
        float acx = an.x + 0.5f * aw;
        float acy = an.y + 0.5f * ah;
        float t0 = ((gcx - acx) / aw) / 0.1f;
        float t1 = ((gcy - acy) / ah) / 0.1f;
        float t2 = __logf(gw / aw) / 0.2f;
        float t3 = __logf(gh / ah) / 0.2f;
        float4 rp = __ldg(((const float4*)reg) + (size_t)b * NA + i);
        float d0 = fabsf(t0 - rp.x);
        float d1 = fabsf(t1 - rp.y);
        float d2 = fabsf(t2 - rp.z);
        float d3 = fabsf(t3 - rp.w);
        const float th = 1.0f / 9.0f;
        reg_acc += (d0 <= th) ? 4.5f * d0 * d0 : d0 - 0.5f / 9.0f;
        reg_acc += (d1 <= th) ? 4.5f * d1 * d1 : d1 - 0.5f / 9.0f;
        reg_acc += (d2 <= th) ? 4.5f * d2 * d2 : d2 - 0.5f / 9.0f;
        reg_acc += (d3 <= th) ? 4.5f * d3 * d3 : d3 - 0.5f / 9.0f;
        atomicOr(&s_used, 1u << arg);
    }

    g_flags[(size_t)b * NA + i] = flag;

    float wr = warp_sum_f(reg_acc);
    int   wn = warp_sum_i(pos ? 1 : 0);
    int w = threadIdx.x >> 5, lane = threadIdx.x & 31;
    if (lane == 0) { sr[w] = wr; sn[w] = wn; }
    __syncthreads();
    if (threadIdx.x == 0) {
        float tr = 0.f; int tn = 0;
#pragma unroll
        for (int k = 0; k < TPB / 32; k++) { tr += sr[k]; tn += sn[k]; }
        int pidx = b * FLAG_BLOCKS + blockIdx.x;
        g_part_reg[pidx]  = tr;
        g_part_np [pidx]  = tn;
        g_part_used[pidx] = s_used;
    }
}

// ---------------------------------------------------------------------------
// Kernel 2: branchless coalesced focal stream (target-0 term for ALL anchors).
// ---------------------------------------------------------------------------
__global__ __launch_bounds__(TPB)
void cls_kernel(const float* __restrict__ cls) {
    const int b = blockIdx.y;
    const float4* base = (const float4*)(cls + (size_t)b * NA * NC);

    float acc = 0.f;   // sum of p^2 * log2(1-p); scaled at the end
    int idx = blockIdx.x * TPB + threadIdx.x;
#pragma unroll
    for (int it = 0; it < (NA * F4R) / (CLS_BLOCKS * TPB); it++) {  // 8 iters
        float4 v = __ldg(base + idx);
        float pv[4] = {v.x, v.y, v.z, v.w};
#pragma unroll
        for (int k = 0; k < 4; k++) {
            float p = fminf(fmaxf(pv[k], 1e-4f), 1.f - 1e-4f);
            float q = 1.f - p;
            acc = fmaf(p * p, __log2f(q), acc);
        }
        idx += CLS_BLOCKS * TPB;
    }

    __shared__ float sc[TPB / 32];
    float wc = warp_sum_f(acc);
    int w = threadIdx.x >> 5, lane = threadIdx.x & 31;
    if (lane == 0) sc[w] = wc;
    __syncthreads();
    if (threadIdx.x == 0) {
        float tc = 0.f;
#pragma unroll
        for (int k = 0; k < TPB / 32; k++) tc += sc[k];
        g_part_cls[b * CLS_BLOCKS + blockIdx.x] = tc * NEG_LN2_075;
    }
}

// ---------------------------------------------------------------------------
// Kernel 3: loc loss + cls corrections + finalize (ticket).
// ---------------------------------------------------------------------------
__global__ __launch_bounds__(TPB)
void pass2_kernel(const float* __restrict__ cls,
                  const float* __restrict__ reg,
                  const float* __restrict__ loc,
                  const float* __restrict__ anc,
                  const float* __restrict__ ann,
                  float* __restrict__ out) {
    const int b = blockIdx.y;
    const int i = blockIdx.x * TPB + threadIdx.x;

    __shared__ float4   sbox[NM];
    __shared__ float    sarea[NM];
    __shared__ unsigned s_used;
    __shared__ unsigned s_mask;
    __shared__ float    sl[TPB / 32], sf[TPB / 32];

    if (threadIdx.x == 0) s_used = 0u;
    __syncthreads();
    {
        unsigned um = g_part_used[b * FLAG_BLOCKS + threadIdx.x];
#pragma unroll
        for (int o = 16; o > 0; o >>= 1) um |= __shfl_xor_sync(0xffffffffu, um, o);
        if ((threadIdx.x & 31) == 0) atomicOr(&s_used, um);
    }
    if (threadIdx.x < NM) {
        const float* a5 = ann + ((size_t)b * NM + threadIdx.x) * 5;
        float4 bx = make_float4(a5[0], a5[1], a5[2], a5[3]);
        sbox[threadIdx.x]  = bx;
        sarea[threadIdx.x] = (bx.z - bx.x) * (bx.w - bx.y);
    }
    __syncthreads();
    if (threadIdx.x == 0) {
        unsigned m = s_used;
        for (int k = 0; k < NM; k++)
            if (ann[((size_t)b * NM + k) * 5 + 4] == -1.0f) m &= ~(1u << k);
        s_mask = m;
    }
    __syncthreads();
    const unsigned mask = s_mask;

    const int8_t flag = g_flags[(size_t)b * NA + i];
    unsigned pm = g_posmask[((size_t)b * NA + i) >> 5];
    const bool pos = (pm >> (i & 31)) & 1u;

    float loc_acc = 0.f;
    float fix_acc = 0.f;

    // cls corrections
    if (flag == -2) {
        // ignore anchor: subtract the whole target-0 row the stream added
        const float4* row = (const float4*)(cls + ((size_t)b * NA + i) * NC);
        float s = 0.f;
#pragma unroll
        for (int j = 0; j < F4R; j++) {
            float4 v = __ldg(row + j);
            float pv[4] = {v.x, v.y, v.z, v.w};
#pragma unroll
            for (int k = 0; k < 4; k++) {
                float p = fminf(fmaxf(pv[k], 1e-4f), 1.f - 1e-4f);
                s = fmaf(p * p, __log2f(1.f - p), s);
            }
        }
        fix_acc = -s * NEG_LN2_075;
    } else if (flag >= 0) {
        // pos anchor: swap label-class term from target-0 to target-1
        float p = __ldg(cls + ((size_t)b * NA + i) * NC + flag);
        p = fminf(fmaxf(p, 1e-4f), 1.f - 1e-4f);
        float q = 1.f - p;
        fix_acc = 0.25f * q * q * (-__logf(p)) - 0.75f * p * p * (-__logf(q));
    }

    if (pos) {
        float4 an = __ldg(((const float4*)anc) + i);
        float aw = an.z - an.x;
        float ah = an.w - an.y;
        float acx = an.x + 0.5f * aw;
        float acy = an.y + 0.5f * ah;
        float4 rp = __ldg(((const float4*)reg) + (size_t)b * NA + i);
        float pcx = acx + rp.x * 0.1f * aw, pcy = acy + rp.y * 0.1f * ah;
        float pw = __expf(rp.z * 0.2f) * aw, ph = __expf(rp.w * 0.2f) * ah;
        float sx1 = fminf(fmaxf(pcx - 0.5f * pw, 0.f), IMG_WH);
        float sy1 = fminf(fmaxf(pcy - 0.5f * ph, 0.f), IMG_WH);
        float sx2 = fminf(fmaxf(pcx + 0.5f * pw, 0.f), IMG_WH);
        float sy2 = fminf(fmaxf(pcy + 0.5f * ph, 0.f), IMG_WH);
        float area_s = (sx2 - sx1) * (sy2 - sy1);

        float best = -1e9f;
#pragma unroll
        for (int m = 0; m < NM; m++) {
            if ((mask >> m) & 1u) {
                float4 bx = sbox[m];
                float iw = fmaxf(fminf(sx2, bx.z) - fmaxf(sx1, bx.x), 0.f);
                float ih = fmaxf(fminf(sy2, bx.w) - fmaxf(sy1, bx.y), 0.f);
                float inter = iw * ih;
                best = fmaxf(best, inter / fmaxf(area_s + sarea[m] - inter, 1e-8f));
            }
        }
        float lp = __ldg(loc + (size_t)b * NA + i);
        float ls = fminf(fmaxf(1.f - fabsf(lp - best), 1e-4f), 1.f - 1e-4f);
        loc_acc = -__logf(ls);
    }

    float wl = warp_sum_f(loc_acc);
    float wf = warp_sum_f(fix_acc);
    int w = threadIdx.x >> 5, lane = threadIdx.x & 31;
    if (lane == 0) { sl[w] = wl; sf[w] = wf; }
    __syncthreads();
    if (threadIdx.x == 0) {
        float tl = 0.f, tf = 0.f;
#pragma unroll
        for (int k = 0; k < TPB / 32; k++) { tl += sl[k]; tf += sf[k]; }
        g_part_loc[b * P2_BLOCKS + blockIdx.x] = tl;
        g_part_fix[b * P2_BLOCKS + blockIdx.x] = tf;
        __threadfence();
    }
    __syncthreads();

    __shared__ int s_last;
    if (threadIdx.x == 0) {
        int t = atomicAdd(&g_ticket, 1);
        s_last = (t == (int)(gridDim.x * gridDim.y) - 1);
    }
    __syncthreads();
    if (!s_last) return;

    __shared__ float f_c[NB], f_r[NB], f_l[NB];
    {
        int wi = threadIdx.x >> 5;
        int ln = threadIdx.x & 31;
        if (wi < NB) {
            float cs = 0.f;
#pragma unroll
            for (int k = 0; k < CLS_BLOCKS / 32; k++)
                cs += g_part_cls[wi * CLS_BLOCKS + k * 32 + ln];
            float rs = 0.f, lsum = 0.f, fsum = 0.f; int np = 0;
#pragma unroll
            for (int k = 0; k < FLAG_BLOCKS / 32; k++) {
                int p = wi * FLAG_BLOCKS + k * 32 + ln;
                rs   += g_part_reg[p];
                np   += g_part_np[p];
                lsum += g_part_loc[p];
                fsum += g_part_fix[p];
            }
            cs = warp_sum_f(cs); rs = warp_sum_f(rs);
            lsum = warp_sum_f(lsum); fsum = warp_sum_f(fsum);
            np = warp_sum_i(np);
            bool v = (ln < NM) && (ann[((size_t)wi * NM + ln) * 5 + 4] != -1.0f);
            bool has_gt = __ballot_sync(0xffffffffu, v) != 0u;
            if (ln == 0) {
                float fnp = (float)np;
                bool ok = has_gt && (np > 0);
                f_c[wi] = has_gt ? (cs + fsum) / fmaxf(fnp, 1.f)   : 0.f;
                f_r[wi] = ok     ? rs / fmaxf(fnp * 4.f, 1.f)      : 0.f;
                f_l[wi] = ok     ? lsum / fmaxf(fnp, 1.f)          : 0.f;
            }
        }
    }
    __syncthreads();
    if (threadIdx.x == 0) {
        float c = 0.f, r = 0.f, l = 0.f;
#pragma unroll
        for (int k = 0; k < NB; k++) { c += f_c[k]; r += f_r[k]; l += f_l[k]; }
        out[0] = c / (float)NB;
        out[1] = r / (float)NB;
        out[2] = l / (float)NB;
        g_ticket = 0;
    }
}

// ---------------------------------------------------------------------------
extern "C" void kernel_launch(void* const* d_in, const int* in_sizes, int n_in,
                              void* d_out, int out_size) {
    const float* cls = (const float*)d_in[0];
    const float* reg = (const float*)d_in[1];
    const float* loc = (const float*)d_in[2];
    const float* anc = (const float*)d_in[3];
    const float* ann = (const float*)d_in[4];
    float* out = (float*)d_out;

    flags_kernel<<<dim3(FLAG_BLOCKS, NB), TPB>>>(reg, anc, ann);
    cls_kernel<<<dim3(CLS_BLOCKS, NB), TPB>>>(cls);
    pass2_kernel<<<dim3(P2_BLOCKS, NB), TPB>>>(cls, reg, loc, anc, ann, out);
}

// round 4
// speedup vs baseline: 1.4748x; 1.2407x over previous
#include <cuda_runtime.h>
#include <cstdint>

#define NB 8
#define NA 65536
#define NC 80
#define NM 32
#define IMG_WH 512.0f
#define TPB 256
#define F4R 20                     // float4 per classification row
#define BLOCKS_X (NA / TPB)        // 256 blocks/image
#define P2_BLOCKS 256
#define LN2 0.6931471805599453f

// ---------------------------------------------------------------------------
// Scratch
// ---------------------------------------------------------------------------
__device__ unsigned g_posmask[NB * NA / 32];
__device__ float    g_part_cls[NB * BLOCKS_X];
__device__ float    g_part_reg[NB * BLOCKS_X];
__device__ int      g_part_np [NB * BLOCKS_X];
__device__ unsigned g_part_used[NB * BLOCKS_X];
__device__ float    g_part_loc[NB * P2_BLOCKS];
__device__ int      g_ticket = 0;

__device__ __forceinline__ float warp_sum_f(float v) {
#pragma unroll
    for (int o = 16; o > 0; o >>= 1) v += __shfl_down_sync(0xffffffffu, v, o);
    return v;
}
__device__ __forceinline__ int warp_sum_i(int v) {
#pragma unroll
    for (int o = 16; o > 0; o >>= 1) v += __shfl_down_sync(0xffffffffu, v, o);
    return v;
}

// ---------------------------------------------------------------------------
// Kernel 1 (fused): flags -> smem, focal cls stream, reg loss, posmask.
// ---------------------------------------------------------------------------
__global__ __launch_bounds__(TPB, 4)
void pass1_kernel(const float* __restrict__ cls,
                  const float* __restrict__ reg,
                  const float* __restrict__ anc,
                  const float* __restrict__ ann) {
    const int b = blockIdx.y;
    const int i = blockIdx.x * TPB + threadIdx.x;   // global anchor

    __shared__ float4   sbox[NM];
    __shared__ float    slbl[NM];
    __shared__ float    sarea_eff[NM];     // 1e30 for invalid boxes
    __shared__ int8_t   sflag[TPB];        // label / -1 neg / -2 ignore
    __shared__ unsigned s_used;
    __shared__ float    sc[TPB / 32], sr[TPB / 32];
    __shared__ int      sn[TPB / 32];

    if (threadIdx.x < NM) {
        const float* a5 = ann + ((size_t)b * NM + threadIdx.x) * 5;
        float4 bx = make_float4(a5[0], a5[1], a5[2], a5[3]);
        float lbl = a5[4];
        sbox[threadIdx.x] = bx;
        slbl[threadIdx.x] = lbl;
        sarea_eff[threadIdx.x] = (lbl == -1.0f) ? 1e30f
                               : (bx.z - bx.x) * (bx.w - bx.y);
    }
    if (threadIdx.x == 0) s_used = 0u;
    __syncthreads();

    const float4 an = __ldg(((const float4*)anc) + i);
    const float aw = an.z - an.x;
    const float ah = an.w - an.y;
    const float area_a = aw * ah;

    // ---- Phase A: pos/neg, division-free, bounded unroll ----
    float maxPos = -1e30f;
    float maxNeg = -1e30f;
#pragma unroll 8
    for (int m = 0; m < NM; m++) {
        float4 bx = sbox[m];
        float iw = fmaxf(fminf(an.z, bx.z) - fmaxf(an.x, bx.x), 0.f);
        float ih = fmaxf(fminf(an.w, bx.w) - fmaxf(an.y, bx.y), 0.f);
        float inter = iw * ih;
        float sab = area_a + sarea_eff[m];
        maxPos = fmaxf(maxPos, fmaf(3.0f, inter, -sab));
        maxNeg = fmaxf(maxNeg, fmaf(3.5f, inter, -sab));
    }
    const bool pos = maxPos >= 0.f;
    const bool neg = maxNeg < 0.f;

    unsigned bal = __ballot_sync(0xffffffffu, pos);
    if ((threadIdx.x & 31) == 0)
        g_posmask[((size_t)b * NA + i) >> 5] = bal;

    float reg_acc = 0.f;
    int flag = neg ? -1 : -2;

    if (pos) {
        // ---- Phase B: first-max argmax (rare), division-free, no unroll ----
        float bi = -1.f, bd = 1.f;
        int arg = 0;
#pragma unroll 1
        for (int m = 0; m < NM; m++) {
            float4 bx = sbox[m];
            float iw = fmaxf(fminf(an.z, bx.z) - fmaxf(an.x, bx.x), 0.f);
            float ih = fmaxf(fminf(an.w, bx.w) - fmaxf(an.y, bx.y), 0.f);
            float inter = iw * ih;
            float area_b = (bx.z - bx.x) * (bx.w - bx.y);
            float den = area_a + area_b - inter;
            bool invalid = (slbl[m] == -1.0f);
            float im = invalid ? -1.f : inter;
            float dm = invalid ?  1.f : den;
            if (im * bd > bi * dm) { bi = im; bd = dm; arg = m; }
        }
        flag = (int)slbl[arg];

        float4 bx = sbox[arg];
        float gwr = bx.z - bx.x;
        float ghr = bx.w - bx.y;
        float gcx = bx.x + 0.5f * gwr;
        float gcy = bx.y + 0.5f * ghr;
        float gw = fmaxf(gwr, 1.f);
        float gh = fmaxf(ghr, 1.f);
        float acx = an.x + 0.5f * aw;
        float acy = an.y + 0.5f * ah;
        float t0 = ((gcx - acx) / aw) / 0.1f;
        float t1 = ((gcy - acy) / ah) / 0.1f;
        float t2 = __logf(gw / aw) / 0.2f;
        float t3 = __logf(gh / ah) / 0.2f;
        float4 rp = __ldg(((const float4*)reg) + (size_t)b * NA + i);
        float d0 = fabsf(t0 - rp.x);
        float d1 = fabsf(t1 - rp.y);
        float d2 = fabsf(t2 - rp.z);
        float d3 = fabsf(t3 - rp.w);
        const float th = 1.0f / 9.0f;
        reg_acc += (d0 <= th) ? 4.5f * d0 * d0 : d0 - 0.5f / 9.0f;
        reg_acc += (d1 <= th) ? 4.5f * d1 * d1 : d1 - 0.5f / 9.0f;
        reg_acc += (d2 <= th) ? 4.5f * d2 * d2 : d2 - 0.5f / 9.0f;
        reg_acc += (d3 <= th) ? 4.5f * d3 * d3 : d3 - 0.5f / 9.0f;
        atomicOr(&s_used, 1u << arg);
    }

    sflag[threadIdx.x] = (int8_t)flag;
    __syncthreads();

    // ---- Phase C: coalesced focal stream over this block's 256 rows ----
    // Block's rows form one contiguous chunk of 5120 float4.
    const float4* rowbase =
        (const float4*)(cls + ((size_t)b * NA + (size_t)blockIdx.x * TPB) * NC);

    float cls_acc = 0.f;   // in log2 units
#pragma unroll 5
    for (int it = 0; it < F4R; it++) {
        int f4i = it * TPB + threadIdx.x;
        int la  = f4i / F4R;               // local anchor 0..255
        int c0  = (f4i - la * F4R) * 4;    // first class of this float4
        int fl  = (int)sflag[la];
        float w0 = (fl == -2) ? 0.f : 0.75f;
        float4 v = __ldg(rowbase + f4i);
        float pv[4] = {v.x, v.y, v.z, v.w};
#pragma unroll
        for (int k = 0; k < 4; k++) {
            float p = fminf(fmaxf(pv[k], 1e-4f), 1.f - 1e-4f);
            bool one = (fl == c0 + k);
            float u = one ? 1.f - p : p;
            float w = one ? 0.25f   : w0;
            cls_acc = fmaf(w * u * u, __log2f(1.f - u), cls_acc);
        }
    }
    cls_acc *= -LN2;

    // ---- block reduction ----
    float wc = warp_sum_f(cls_acc);
    float wr = warp_sum_f(reg_acc);
    int   wn = warp_sum_i(pos ? 1 : 0);
    int w = threadIdx.x >> 5, lane = threadIdx.x & 31;
    if (lane == 0) { sc[w] = wc; sr[w] = wr; sn[w] = wn; }
    __syncthreads();
    if (threadIdx.x == 0) {
        float tc = 0.f, tr = 0.f; int tn = 0;
#pragma unroll
        for (int k = 0; k < TPB / 32; k++) { tc += sc[k]; tr += sr[k]; tn += sn[k]; }
        int pidx = b * BLOCKS_X + blockIdx.x;
        g_part_cls[pidx]  = tc;
        g_part_reg[pidx]  = tr;
        g_part_np [pidx]  = tn;
        g_part_used[pidx] = s_used;
    }
}

// ---------------------------------------------------------------------------
// Kernel 2: loc loss + ticket-based finalize.
// ---------------------------------------------------------------------------
__global__ __launch_bounds__(TPB)
void pass2_kernel(const float* __restrict__ reg,
                  const float* __restrict__ loc,
                  const float* __restrict__ anc,
                  const float* __restrict__ ann,
                  float* __restrict__ out) {
    const int b = blockIdx.y;
    const int i = blockIdx.x * TPB + threadIdx.x;

    __shared__ float4   sbox[NM];
    __shared__ float    sarea[NM];
    __shared__ unsigned s_used;
    __shared__ unsigned s_mask;
    __shared__ float    sl[TPB / 32];

    if (threadIdx.x == 0) s_used = 0u;
    __syncthreads();
    {
        unsigned um = g_part_used[b * BLOCKS_X + threadIdx.x];
#pragma unroll
        for (int o = 16; o > 0; o >>= 1) um |= __shfl_xor_sync(0xffffffffu, um, o);
        if ((threadIdx.x & 31) == 0) atomicOr(&s_used, um);
    }
    if (threadIdx.x < NM) {
        const float* a5 = ann + ((size_t)b * NM + threadIdx.x) * 5;
        float4 bx = make_float4(a5[0], a5[1], a5[2], a5[3]);
        sbox[threadIdx.x]  = bx;
        sarea[threadIdx.x] = (bx.z - bx.x) * (bx.w - bx.y);
    }
    __syncthreads();
    if (threadIdx.x == 0) {
        unsigned m = s_used;
        for (int k = 0; k < NM; k++)
            if (ann[((size_t)b * NM + k) * 5 + 4] == -1.0f) m &= ~(1u << k);
        s_mask = m;
    }
    __syncthreads();
    const unsigned mask = s_mask;

    unsigned pm = g_posmask[((size_t)b * NA + i) >> 5];
    const bool pos = (pm >> (i & 31)) & 1u;

    float loc_acc = 0.f;
    if (pos) {
        float4 an = __ldg(((const float4*)anc) + i);
        float aw = an.z - an.x;
        float ah = an.w - an.y;
        float acx = an.x + 0.5f * aw;
        float acy = an.y + 0.5f * ah;
        float4 rp = __ldg(((const float4*)reg) + (size_t)b * NA + i);
        float pcx = acx + rp.x * 0.1f * aw, pcy = acy + rp.y * 0.1f * ah;
        float pw = __expf(rp.z * 0.2f) * aw, ph = __expf(rp.w * 0.2f) * ah;
        float sx1 = fminf(fmaxf(pcx - 0.5f * pw, 0.f), IMG_WH);
        float sy1 = fminf(fmaxf(pcy - 0.5f * ph, 0.f), IMG_WH);
        float sx2 = fminf(fmaxf(pcx + 0.5f * pw, 0.f), IMG_WH);
        float sy2 = fminf(fmaxf(pcy + 0.5f * ph, 0.f), IMG_WH);
        float area_s = (sx2 - sx1) * (sy2 - sy1);

        float best = -1e9f;
#pragma unroll 1
        for (int m = 0; m < NM; m++) {
            if ((mask >> m) & 1u) {
                float4 bx = sbox[m];
                float iw = fmaxf(fminf(sx2, bx.z) - fmaxf(sx1, bx.x), 0.f);
                float ih = fmaxf(fminf(sy2, bx.w) - fmaxf(sy1, bx.y), 0.f);
                float inter = iw * ih;
                best = fmaxf(best, inter / fmaxf(area_s + sarea[m] - inter, 1e-8f));
            }
        }
        float lp = __ldg(loc + (size_t)b * NA + i);
        float ls = fminf(fmaxf(1.f - fabsf(lp - best), 1e-4f), 1.f - 1e-4f);
        loc_acc = -__logf(ls);
    }

    float wl = warp_sum_f(loc_acc);
    int w = threadIdx.x >> 5, lane = threadIdx.x & 31;
    if (lane == 0) sl[w] = wl;
    __syncthreads();
    if (threadIdx.x == 0) {
        g_part_loc[b * P2_BLOCKS + blockIdx.x] = [&] {
            float tl = 0.f;
#pragma unroll
            for (int k = 0; k < TPB / 32; k++) tl += sl[k];
            return tl;
        }();
        __threadfence();
    }
    __syncthreads();

    __shared__ int s_last;
    if (threadIdx.x == 0) {
        int t = atomicAdd(&g_ticket, 1);
        s_last = (t == (int)(gridDim.x * gridDim.y) - 1);
    }
    __syncthreads();
    if (!s_last) return;

    __shared__ float f_c[NB], f_r[NB], f_l[NB];
    {
        int wi = threadIdx.x >> 5;
        int ln = threadIdx.x & 31;
        if (wi < NB) {
            float cs = 0.f, rs = 0.f, lsum = 0.f; int np = 0;
#pragma unroll
            for (int k = 0; k < BLOCKS_X / 32; k++) {
                int p = wi * BLOCKS_X + k * 32 + ln;
                cs   += g_part_cls[p];
                rs   += g_part_reg[p];
                np   += g_part_np[p];
                lsum += g_part_loc[p];
            }
            cs = warp_sum_f(cs); rs = warp_sum_f(rs);
            lsum = warp_sum_f(lsum); np = warp_sum_i(np);
            bool v = (ln < NM) && (ann[((size_t)wi * NM + ln) * 5 + 4] != -1.0f);
            bool has_gt = __ballot_sync(0xffffffffu, v) != 0u;
            if (ln == 0) {
                float fnp = (float)np;
                bool ok = has_gt && (np > 0);
                f_c[wi] = has_gt ? cs / fmaxf(fnp, 1.f)       : 0.f;
                f_r[wi] = ok     ? rs / fmaxf(fnp * 4.f, 1.f) : 0.f;
                f_l[wi] = ok     ? lsum / fmaxf(fnp, 1.f)     : 0.f;
            }
        }
    }
    __syncthreads();
    if (threadIdx.x == 0) {
        float c = 0.f, r = 0.f, l = 0.f;
#pragma unroll
        for (int k = 0; k < NB; k++) { c += f_c[k]; r += f_r[k]; l += f_l[k]; }
        out[0] = c / (float)NB;
        out[1] = r / (float)NB;
        out[2] = l / (float)NB;
        g_ticket = 0;
    }
}

// ---------------------------------------------------------------------------
extern "C" void kernel_launch(void* const* d_in, const int* in_sizes, int n_in,
                              void* d_out, int out_size) {
    const float* cls = (const float*)d_in[0];
    const float* reg = (const float*)d_in[1];
    const float* loc = (const float*)d_in[2];
    const float* anc = (const float*)d_in[3];
    const float* ann = (const float*)d_in[4];
    float* out = (float*)d_out;

    pass1_kernel<<<dim3(BLOCKS_X, NB), TPB>>>(cls, reg, anc, ann);
    pass2_kernel<<<dim3(P2_BLOCKS, NB), TPB>>>(reg, loc, anc, ann, out);
}

// round 5
// speedup vs baseline: 1.7486x; 1.1857x over previous
#include <cuda_runtime.h>
#include <cstdint>

#define NB 8
#define NA 65536
#define NC 80
#define NM 32
#define IMG_WH 512.0f
#define TPB 256
#define F4R 20                     // float4 per classification row
#define BLOCKS_X (NA / TPB)        // 256 blocks/image
#define P2X 16                     // pass2 x-blocks per image
#define LN2 0.6931471805599453f

// ---------------------------------------------------------------------------
// Scratch
// ---------------------------------------------------------------------------
__device__ float    g_part_cls[NB * BLOCKS_X];
__device__ float    g_part_reg[NB * BLOCKS_X];
__device__ int      g_part_np [NB * BLOCKS_X];
__device__ unsigned g_part_used[NB * BLOCKS_X];
__device__ float    g_part_loc[NB * P2X];
__device__ int      g_poscnt[NB];          // zero-init; reset by pass2 finalize
__device__ int      g_poslist[NB * NA];
__device__ int      g_ticket = 0;

__device__ __forceinline__ float warp_sum_f(float v) {
#pragma unroll
    for (int o = 16; o > 0; o >>= 1) v += __shfl_down_sync(0xffffffffu, v, o);
    return v;
}
__device__ __forceinline__ int warp_sum_i(int v) {
#pragma unroll
    for (int o = 16; o > 0; o >>= 1) v += __shfl_down_sync(0xffffffffu, v, o);
    return v;
}

// ---------------------------------------------------------------------------
// Kernel 1 (fused): flags -> smem, focal cls stream, reg loss, pos compaction.
// ---------------------------------------------------------------------------
__global__ __launch_bounds__(TPB, 4)
void pass1_kernel(const float* __restrict__ cls,
                  const float* __restrict__ reg,
                  const float* __restrict__ anc,
                  const float* __restrict__ ann) {
    const int b = blockIdx.y;
    const int i = blockIdx.x * TPB + threadIdx.x;   // global anchor

    __shared__ float4   sbox[NM];
    __shared__ float    slbl[NM];
    __shared__ float    sarea_eff[NM];     // 1e30 for invalid boxes
    __shared__ int8_t   sflag[TPB];        // label / -1 neg / -2 ignore
    __shared__ unsigned s_used;
    __shared__ float    sc[TPB / 32], sr[TPB / 32];
    __shared__ int      sn[TPB / 32];

    if (threadIdx.x < NM) {
        const float* a5 = ann + ((size_t)b * NM + threadIdx.x) * 5;
        float4 bx = make_float4(a5[0], a5[1], a5[2], a5[3]);
        float lbl = a5[4];
        sbox[threadIdx.x] = bx;
        slbl[threadIdx.x] = lbl;
        sarea_eff[threadIdx.x] = (lbl == -1.0f) ? 1e30f
                               : (bx.z - bx.x) * (bx.w - bx.y);
    }
    if (threadIdx.x == 0) s_used = 0u;
    __syncthreads();

    const float4 an = __ldg(((const float4*)anc) + i);
    const float aw = an.z - an.x;
    const float ah = an.w - an.y;
    const float area_a = aw * ah;

    // ---- Phase A: pos/neg, division-free ----
    float maxPos = -1e30f;
    float maxNeg = -1e30f;
#pragma unroll 8
    for (int m = 0; m < NM; m++) {
        float4 bx = sbox[m];
        float iw = fmaxf(fminf(an.z, bx.z) - fmaxf(an.x, bx.x), 0.f);
        float ih = fmaxf(fminf(an.w, bx.w) - fmaxf(an.y, bx.y), 0.f);
        float inter = iw * ih;
        float sab = area_a + sarea_eff[m];
        maxPos = fmaxf(maxPos, fmaf(3.0f, inter, -sab));
        maxNeg = fmaxf(maxNeg, fmaf(3.5f, inter, -sab));
    }
    const bool pos = maxPos >= 0.f;
    const bool neg = maxNeg < 0.f;

    float reg_acc = 0.f;
    int flag = neg ? -1 : -2;

    if (pos) {
        // pos compaction for pass2
        int slot = atomicAdd(&g_poscnt[b], 1);
        g_poslist[(size_t)b * NA + slot] = i;

        // ---- Phase B: first-max argmax (rare), division-free ----
        float bi = -1.f, bd = 1.f;
        int arg = 0;
#pragma unroll 1
        for (int m = 0; m < NM; m++) {
            float4 bx = sbox[m];
            float iw = fmaxf(fminf(an.z, bx.z) - fmaxf(an.x, bx.x), 0.f);
            float ih = fmaxf(fminf(an.w, bx.w) - fmaxf(an.y, bx.y), 0.f);
            float inter = iw * ih;
            float area_b = (bx.z - bx.x) * (bx.w - bx.y);
            float den = area_a + area_b - inter;
            bool invalid = (slbl[m] == -1.0f);
            float im = invalid ? -1.f : inter;
            float dm = invalid ?  1.f : den;
            if (im * bd > bi * dm) { bi = im; bd = dm; arg = m; }
        }
        flag = (int)slbl[arg];

        float4 bx = sbox[arg];
        float gwr = bx.z - bx.x;
        float ghr = bx.w - bx.y;
        float gcx = bx.x + 0.5f * gwr;
        float gcy = bx.y + 0.5f * ghr;
        float gw = fmaxf(gwr, 1.f);
        float gh = fmaxf(ghr, 1.f);
        float acx = an.x + 0.5f * aw;
        float acy = an.y + 0.5f * ah;
        float t0 = ((gcx - acx) / aw) / 0.1f;
        float t1 = ((gcy - acy) / ah) / 0.1f;
        float t2 = __logf(gw / aw) / 0.2f;
        float t3 = __logf(gh / ah) / 0.2f;
        float4 rp = __ldg(((const float4*)reg) + (size_t)b * NA + i);
        float d0 = fabsf(t0 - rp.x);
        float d1 = fabsf(t1 - rp.y);
        float d2 = fabsf(t2 - rp.z);
        float d3 = fabsf(t3 - rp.w);
        const float th = 1.0f / 9.0f;
        reg_acc += (d0 <= th) ? 4.5f * d0 * d0 : d0 - 0.5f / 9.0f;
        reg_acc += (d1 <= th) ? 4.5f * d1 * d1 : d1 - 0.5f / 9.0f;
        reg_acc += (d2 <= th) ? 4.5f * d2 * d2 : d2 - 0.5f / 9.0f;
        reg_acc += (d3 <= th) ? 4.5f * d3 * d3 : d3 - 0.5f / 9.0f;
        atomicOr(&s_used, 1u << arg);
    }

    sflag[threadIdx.x] = (int8_t)flag;
    __syncthreads();

    // ---- Phase C: coalesced focal stream over this block's 256 rows ----
    const float4* rowbase =
        (const float4*)(cls + ((size_t)b * NA + (size_t)blockIdx.x * TPB) * NC);

    float cls_acc = 0.f;   // in log2 units
#pragma unroll 5
    for (int it = 0; it < F4R; it++) {
        int f4i = it * TPB + threadIdx.x;
        int la  = f4i / F4R;
        int c0  = (f4i - la * F4R) * 4;
        int fl  = (int)sflag[la];
        float w0 = (fl == -2) ? 0.f : 0.75f;
        float4 v = __ldg(rowbase + f4i);
        float pv[4] = {v.x, v.y, v.z, v.w};
#pragma unroll
        for (int k = 0; k < 4; k++) {
            float p = fminf(fmaxf(pv[k], 1e-4f), 1.f - 1e-4f);
            bool one = (fl == c0 + k);
            float u = one ? 1.f - p : p;
            float w = one ? 0.25f   : w0;
            cls_acc = fmaf(w * u * u, __log2f(1.f - u), cls_acc);
        }
    }
    cls_acc *= -LN2;

    // ---- block reduction ----
    float wc = warp_sum_f(cls_acc);
    float wr = warp_sum_f(reg_acc);
    int   wn = warp_sum_i(pos ? 1 : 0);
    int w = threadIdx.x >> 5, lane = threadIdx.x & 31;
    if (lane == 0) { sc[w] = wc; sr[w] = wr; sn[w] = wn; }
    __syncthreads();
    if (threadIdx.x == 0) {
        float tc = 0.f, tr = 0.f; int tn = 0;
#pragma unroll
        for (int k = 0; k < TPB / 32; k++) { tc += sc[k]; tr += sr[k]; tn += sn[k]; }
        int pidx = b * BLOCKS_X + blockIdx.x;
        g_part_cls[pidx]  = tc;
        g_part_reg[pidx]  = tr;
        g_part_np [pidx]  = tn;
        g_part_used[pidx] = s_used;
    }
}

// ---------------------------------------------------------------------------
// Kernel 2: loc loss over compacted pos list + ticket finalize (128 blocks).
// ---------------------------------------------------------------------------
__global__ __launch_bounds__(TPB)
void pass2_kernel(const float* __restrict__ reg,
                  const float* __restrict__ loc,
                  const float* __restrict__ anc,
                  const float* __restrict__ ann,
                  float* __restrict__ out) {
    const int b = blockIdx.y;

    __shared__ float4   sbox[NM];
    __shared__ float    sarea[NM];
    __shared__ unsigned s_used;
    __shared__ unsigned s_mask;
    __shared__ float    sl[TPB / 32];

    if (threadIdx.x == 0) s_used = 0u;
    __syncthreads();
    {
        unsigned um = g_part_used[b * BLOCKS_X + threadIdx.x];
#pragma unroll
        for (int o = 16; o > 0; o >>= 1) um |= __shfl_xor_sync(0xffffffffu, um, o);
        if ((threadIdx.x & 31) == 0) atomicOr(&s_used, um);
    }
    if (threadIdx.x < NM) {
        const float* a5 = ann + ((size_t)b * NM + threadIdx.x) * 5;
        float4 bx = make_float4(a5[0], a5[1], a5[2], a5[3]);
        sbox[threadIdx.x]  = bx;
        sarea[threadIdx.x] = (bx.z - bx.x) * (bx.w - bx.y);
    }
    __syncthreads();
    if (threadIdx.x == 0) {
        unsigned m = s_used;
        for (int k = 0; k < NM; k++)
            if (ann[((size_t)b * NM + k) * 5 + 4] == -1.0f) m &= ~(1u << k);
        s_mask = m;
    }
    __syncthreads();
    const unsigned mask = s_mask;
    const int n = g_poscnt[b];

    float loc_acc = 0.f;
    for (int j = blockIdx.x * TPB + threadIdx.x; j < n; j += P2X * TPB) {
        int i = g_poslist[(size_t)b * NA + j];
        float4 an = __ldg(((const float4*)anc) + i);
        float aw = an.z - an.x;
        float ah = an.w - an.y;
        float acx = an.x + 0.5f * aw;
        float acy = an.y + 0.5f * ah;
        float4 rp = __ldg(((const float4*)reg) + (size_t)b * NA + i);
        float pcx = acx + rp.x * 0.1f * aw, pcy = acy + rp.y * 0.1f * ah;
        float pw = __expf(rp.z * 0.2f) * aw, ph = __expf(rp.w * 0.2f) * ah;
        float sx1 = fminf(fmaxf(pcx - 0.5f * pw, 0.f), IMG_WH);
        float sy1 = fminf(fmaxf(pcy - 0.5f * ph, 0.f), IMG_WH);
        float sx2 = fminf(fmaxf(pcx + 0.5f * pw, 0.f), IMG_WH);
        float sy2 = fminf(fmaxf(pcy + 0.5f * ph, 0.f), IMG_WH);
        float area_s = (sx2 - sx1) * (sy2 - sy1);

        float best = -1e9f;
#pragma unroll 1
        for (int m = 0; m < NM; m++) {
            if ((mask >> m) & 1u) {
                float4 bx = sbox[m];
                float iw = fmaxf(fminf(sx2, bx.z) - fmaxf(sx1, bx.x), 0.f);
                float ih = fmaxf(fminf(sy2, bx.w) - fmaxf(sy1, bx.y), 0.f);
                float inter = iw * ih;
                best = fmaxf(best, inter / fmaxf(area_s + sarea[m] - inter, 1e-8f));
            }
        }
        float lp = __ldg(loc + (size_t)b * NA + i);
        float ls = fminf(fmaxf(1.f - fabsf(lp - best), 1e-4f), 1.f - 1e-4f);
        loc_acc += -__logf(ls);
    }

    float wl = warp_sum_f(loc_acc);
    int w = threadIdx.x >> 5, lane = threadIdx.x & 31;
    if (lane == 0) sl[w] = wl;
    __syncthreads();
    if (threadIdx.x == 0) {
        float tl = 0.f;
#pragma unroll
        for (int k = 0; k < TPB / 32; k++) tl += sl[k];
        g_part_loc[b * P2X + blockIdx.x] = tl;
        __threadfence();
    }
    __syncthreads();

    __shared__ int s_last;
    if (threadIdx.x == 0) {
        int t = atomicAdd(&g_ticket, 1);
        s_last = (t == (int)(gridDim.x * gridDim.y) - 1);
    }
    __syncthreads();
    if (!s_last) return;

    __shared__ float f_c[NB], f_r[NB], f_l[NB];
    {
        int wi = threadIdx.x >> 5;
        int ln = threadIdx.x & 31;
        if (wi < NB) {
            float cs = 0.f, rs = 0.f; int np = 0;
#pragma unroll
            for (int k = 0; k < BLOCKS_X / 32; k++) {
                int p = wi * BLOCKS_X + k * 32 + ln;
                cs += g_part_cls[p];
                rs += g_part_reg[p];
                np += g_part_np[p];
            }
            float lsum = (ln < P2X) ? g_part_loc[wi * P2X + ln] : 0.f;
            cs = warp_sum_f(cs); rs = warp_sum_f(rs);
            lsum = warp_sum_f(lsum); np = warp_sum_i(np);
            bool v = (ln < NM) && (ann[((size_t)wi * NM + ln) * 5 + 4] != -1.0f);
            bool has_gt = __ballot_sync(0xffffffffu, v) != 0u;
            if (ln == 0) {
                float fnp = (float)np;
                bool ok = has_gt && (np > 0);
                f_c[wi] = has_gt ? cs / fmaxf(fnp, 1.f)       : 0.f;
                f_r[wi] = ok     ? rs / fmaxf(fnp * 4.f, 1.f) : 0.f;
                f_l[wi] = ok     ? lsum / fmaxf(fnp, 1.f)     : 0.f;
            }
        }
    }
    __syncthreads();
    if (threadIdx.x == 0) {
        float c = 0.f, r = 0.f, l = 0.f;
#pragma unroll
        for (int k = 0; k < NB; k++) { c += f_c[k]; r += f_r[k]; l += f_l[k]; }
        out[0] = c / (float)NB;
        out[1] = r / (float)NB;
        out[2] = l / (float)NB;
        g_ticket = 0;
#pragma unroll
        for (int k = 0; k < NB; k++) g_poscnt[k] = 0;   // reset for graph replay
    }
}

// ---------------------------------------------------------------------------
extern "C" void kernel_launch(void* const* d_in, const int* in_sizes, int n_in,
                              void* d_out, int out_size) {
    const float* cls = (const float*)d_in[0];
    const float* reg = (const float*)d_in[1];
    const float* loc = (const float*)d_in[2];
    const float* anc = (const float*)d_in[3];
    const float* ann = (const float*)d_in[4];
    float* out = (float*)d_out;

    pass1_kernel<<<dim3(BLOCKS_X, NB), TPB>>>(cls, reg, anc, ann);
    pass2_kernel<<<dim3(P2X, NB), TPB>>>(reg, loc, anc, ann, out);
}

// round 6
// speedup vs baseline: 2.0512x; 1.1730x over previous
#include <cuda_runtime.h>
#include <cstdint>

#define NB 8
#define NA 65536
#define NC 80
#define NM 32
#define IMG_WH 512.0f
#define TPB 256
#define F4R 20                     // float4 per classification row
#define BLOCKS_X (NA / TPB)        // 256 blocks/image
#define P2X 16                     // pass2 x-blocks per image
#define LN2 0.6931471805599453f

// ---------------------------------------------------------------------------
// Scratch
// ---------------------------------------------------------------------------
__device__ float    g_part_cls[NB * BLOCKS_X];
__device__ float    g_part_reg[NB * BLOCKS_X];
__device__ int      g_part_np [NB * BLOCKS_X];
__device__ float    g_part_loc[NB * P2X];
__device__ unsigned g_used[NB];            // atomicOr from pass1; reset in finalize
__device__ int      g_poscnt[NB];          // reset in finalize
__device__ float4   g_pos_an[NB * NA];     // self-contained pos records
__device__ float4   g_pos_rp[NB * NA];
__device__ float    g_pos_lp[NB * NA];
__device__ int      g_ticket = 0;

__device__ __forceinline__ float warp_sum_f(float v) {
#pragma unroll
    for (int o = 16; o > 0; o >>= 1) v += __shfl_down_sync(0xffffffffu, v, o);
    return v;
}
__device__ __forceinline__ int warp_sum_i(int v) {
#pragma unroll
    for (int o = 16; o > 0; o >>= 1) v += __shfl_down_sync(0xffffffffu, v, o);
    return v;
}

// ---------------------------------------------------------------------------
// Kernel 1 (fused): flags, focal cls stream (+label fix), reg loss, pos records.
// ---------------------------------------------------------------------------
__global__ __launch_bounds__(TPB, 4)
void pass1_kernel(const float* __restrict__ cls,
                  const float* __restrict__ reg,
                  const float* __restrict__ loc,
                  const float* __restrict__ anc,
                  const float* __restrict__ ann) {
    const int b = blockIdx.y;
    const int i = blockIdx.x * TPB + threadIdx.x;   // global anchor

    __shared__ float4   sbox[NM];
    __shared__ float    slbl[NM];
    __shared__ float    sarea_eff[NM];     // 1e30 for invalid boxes
    __shared__ float    sw0[TPB];          // per-anchor cls weight: 0.75 or 0
    __shared__ unsigned s_used;
    __shared__ float    sc[TPB / 32], sr[TPB / 32];
    __shared__ int      sn[TPB / 32];

    if (threadIdx.x < NM) {
        const float* a5 = ann + ((size_t)b * NM + threadIdx.x) * 5;
        float4 bx = make_float4(a5[0], a5[1], a5[2], a5[3]);
        float lbl = a5[4];
        sbox[threadIdx.x] = bx;
        slbl[threadIdx.x] = lbl;
        sarea_eff[threadIdx.x] = (lbl == -1.0f) ? 1e30f
                               : (bx.z - bx.x) * (bx.w - bx.y);
    }
    if (threadIdx.x == 0) s_used = 0u;
    __syncthreads();

    const float4 an = __ldg(((const float4*)anc) + i);
    const float aw = an.z - an.x;
    const float ah = an.w - an.y;
    const float area_a = aw * ah;

    // ---- Phase A: pos/neg, division-free ----
    float maxPos = -1e30f;
    float maxNeg = -1e30f;
#pragma unroll 8
    for (int m = 0; m < NM; m++) {
        float4 bx = sbox[m];
        float iw = fmaxf(fminf(an.z, bx.z) - fmaxf(an.x, bx.x), 0.f);
        float ih = fmaxf(fminf(an.w, bx.w) - fmaxf(an.y, bx.y), 0.f);
        float inter = iw * ih;
        float sab = area_a + sarea_eff[m];
        maxPos = fmaxf(maxPos, fmaf(3.0f, inter, -sab));
        maxNeg = fmaxf(maxNeg, fmaf(3.5f, inter, -sab));
    }
    const bool pos = maxPos >= 0.f;
    const bool neg = maxNeg < 0.f;

    float reg_acc = 0.f;
    float cls_fix = 0.f;

    if (pos) {
        // ---- Phase B: first-max argmax (rare), division-free ----
        float bi = -1.f, bd = 1.f;
        int arg = 0;
#pragma unroll 1
        for (int m = 0; m < NM; m++) {
            float4 bx = sbox[m];
            float iw = fmaxf(fminf(an.z, bx.z) - fmaxf(an.x, bx.x), 0.f);
            float ih = fmaxf(fminf(an.w, bx.w) - fmaxf(an.y, bx.y), 0.f);
            float inter = iw * ih;
            float area_b = (bx.z - bx.x) * (bx.w - bx.y);
            float den = area_a + area_b - inter;
            bool invalid = (slbl[m] == -1.0f);
            float im = invalid ? -1.f : inter;
            float dm = invalid ?  1.f : den;
            if (im * bd > bi * dm) { bi = im; bd = dm; arg = m; }
        }
        const int lbl = (int)slbl[arg];

        // cls label-class fix: stream adds 0.75 p^2 (-log(1-p)); want 0.25 (1-p)^2 (-log p)
        {
            float p = __ldg(cls + ((size_t)b * NA + i) * NC + lbl);
            p = fminf(fmaxf(p, 1e-4f), 1.f - 1e-4f);
            float q = 1.f - p;
            cls_fix = 0.25f * q * q * (-__logf(p)) - 0.75f * p * p * (-__logf(q));
        }

        // self-contained pos record
        float4 rp = __ldg(((const float4*)reg) + (size_t)b * NA + i);
        {
            int slot = atomicAdd(&g_poscnt[b], 1);
            size_t s = (size_t)b * NA + slot;
            g_pos_an[s] = an;
            g_pos_rp[s] = rp;
            g_pos_lp[s] = __ldg(loc + (size_t)b * NA + i);
        }

        // reg loss
        float4 bx = sbox[arg];
        float gwr = bx.z - bx.x;
        float ghr = bx.w - bx.y;
        float gcx = bx.x + 0.5f * gwr;
        float gcy = bx.y + 0.5f * ghr;
        float gw = fmaxf(gwr, 1.f);
        float gh = fmaxf(ghr, 1.f);
        float acx = an.x + 0.5f * aw;
        float acy = an.y + 0.5f * ah;
        float t0 = ((gcx - acx) / aw) / 0.1f;
        float t1 = ((gcy - acy) / ah) / 0.1f;
        float t2 = __logf(gw / aw) / 0.2f;
        float t3 = __logf(gh / ah) / 0.2f;
        float d0 = fabsf(t0 - rp.x);
        float d1 = fabsf(t1 - rp.y);
        float d2 = fabsf(t2 - rp.z);
        float d3 = fabsf(t3 - rp.w);
        const float th = 1.0f / 9.0f;
        reg_acc += (d0 <= th) ? 4.5f * d0 * d0 : d0 - 0.5f / 9.0f;
        reg_acc += (d1 <= th) ? 4.5f * d1 * d1 : d1 - 0.5f / 9.0f;
        reg_acc += (d2 <= th) ? 4.5f * d2 * d2 : d2 - 0.5f / 9.0f;
        reg_acc += (d3 <= th) ? 4.5f * d3 * d3 : d3 - 0.5f / 9.0f;
        atomicOr(&s_used, 1u << arg);
    }

    // weight for the streaming term: 0 for ignore, 0.75 otherwise
    sw0[threadIdx.x] = (!pos && !neg) ? 0.f : 0.75f;
    __syncthreads();

    if (threadIdx.x == 0 && s_used) atomicOr(&g_used[b], s_used);

    // ---- Phase C: coalesced branch-free focal stream ----
    const float4* rowbase =
        (const float4*)(cls + ((size_t)b * NA + (size_t)blockIdx.x * TPB) * NC);

    float cls_acc = 0.f;   // log2 units
#pragma unroll 5
    for (int it = 0; it < F4R; it++) {
        int f4i = it * TPB + threadIdx.x;
        int la  = f4i / F4R;
        float w0 = sw0[la];
        float4 v = __ldg(rowbase + f4i);
        float s4;
        {
            float p = fminf(fmaxf(v.x, 1e-4f), 1.f - 1e-4f);
            s4 = p * p * __log2f(1.f - p);
        }
        {
            float p = fminf(fmaxf(v.y, 1e-4f), 1.f - 1e-4f);
            s4 = fmaf(p * p, __log2f(1.f - p), s4);
        }
        {
            float p = fminf(fmaxf(v.z, 1e-4f), 1.f - 1e-4f);
            s4 = fmaf(p * p, __log2f(1.f - p), s4);
        }
        {
            float p = fminf(fmaxf(v.w, 1e-4f), 1.f - 1e-4f);
            s4 = fmaf(p * p, __log2f(1.f - p), s4);
        }
        cls_acc = fmaf(w0, s4, cls_acc);
    }
    cls_acc = fmaf(cls_acc, -LN2, cls_fix);

    // ---- block reduction ----
    float wc = warp_sum_f(cls_acc);
    float wr = warp_sum_f(reg_acc);
    int   wn = warp_sum_i((maxPos >= 0.f) ? 1 : 0);
    int w = threadIdx.x >> 5, lane = threadIdx.x & 31;
    if (lane == 0) { sc[w] = wc; sr[w] = wr; sn[w] = wn; }
    __syncthreads();
    if (threadIdx.x == 0) {
        float tc = 0.f, tr = 0.f; int tn = 0;
#pragma unroll
        for (int k = 0; k < TPB / 32; k++) { tc += sc[k]; tr += sr[k]; tn += sn[k]; }
        int pidx = b * BLOCKS_X + blockIdx.x;
        g_part_cls[pidx] = tc;
        g_part_reg[pidx] = tr;
        g_part_np [pidx] = tn;
    }
}

// ---------------------------------------------------------------------------
// Kernel 2: loc loss over pos records + ticket finalize (128 blocks).
// ---------------------------------------------------------------------------
__global__ __launch_bounds__(TPB)
void pass2_kernel(const float* __restrict__ ann, float* __restrict__ out) {
    const int b = blockIdx.y;
    const int n = g_poscnt[b];

    __shared__ float4   sbox[NM];
    __shared__ float    sarea[NM];
    __shared__ unsigned s_mask;
    __shared__ float    sl[TPB / 32];

    if (threadIdx.x < 32) {
        bool valid = false;
        if (threadIdx.x < NM) {
            const float* a5 = ann + ((size_t)b * NM + threadIdx.x) * 5;
            float4 bx = make_float4(a5[0], a5[1], a5[2], a5[3]);
            sbox[threadIdx.x]  = bx;
            sarea[threadIdx.x] = (bx.z - bx.x) * (bx.w - bx.y);
            valid = (a5[4] != -1.0f);
        }
        unsigned vm = __ballot_sync(0xffffffffu, valid);
        if (threadIdx.x == 0) s_mask = vm & g_used[b];
    }
    __syncthreads();
    const unsigned mask = s_mask;

    float loc_acc = 0.f;
    for (int j = blockIdx.x * TPB + threadIdx.x; j < n; j += P2X * TPB) {
        size_t s = (size_t)b * NA + j;
        float4 an = g_pos_an[s];
        float4 rp = g_pos_rp[s];
        float  lp = g_pos_lp[s];
        float aw = an.z - an.x;
        float ah = an.w - an.y;
        float acx = an.x + 0.5f * aw;
        float acy = an.y + 0.5f * ah;
        float pcx = acx + rp.x * 0.1f * aw, pcy = acy + rp.y * 0.1f * ah;
        float pw = __expf(rp.z * 0.2f) * aw, ph = __expf(rp.w * 0.2f) * ah;
        float sx1 = fminf(fmaxf(pcx - 0.5f * pw, 0.f), IMG_WH);
        float sy1 = fminf(fmaxf(pcy - 0.5f * ph, 0.f), IMG_WH);
        float sx2 = fminf(fmaxf(pcx + 0.5f * pw, 0.f), IMG_WH);
        float sy2 = fminf(fmaxf(pcy + 0.5f * ph, 0.f), IMG_WH);
        float area_s = (sx2 - sx1) * (sy2 - sy1);

        float best = -1e9f;
#pragma unroll 1
        for (int m = 0; m < NM; m++) {
            if ((mask >> m) & 1u) {
                float4 bx = sbox[m];
                float iw = fmaxf(fminf(sx2, bx.z) - fmaxf(sx1, bx.x), 0.f);
                float ih = fmaxf(fminf(sy2, bx.w) - fmaxf(sy1, bx.y), 0.f);
                float inter = iw * ih;
                best = fmaxf(best, inter / fmaxf(area_s + sarea[m] - inter, 1e-8f));
            }
        }
        float ls = fminf(fmaxf(1.f - fabsf(lp - best), 1e-4f), 1.f - 1e-4f);
        loc_acc += -__logf(ls);
    }

    float wl = warp_sum_f(loc_acc);
    int w = threadIdx.x >> 5, lane = threadIdx.x & 31;
    if (lane == 0) sl[w] = wl;
    __syncthreads();
    if (threadIdx.x == 0) {
        float tl = 0.f;
#pragma unroll
        for (int k = 0; k < TPB / 32; k++) tl += sl[k];
        g_part_loc[b * P2X + blockIdx.x] = tl;
        __threadfence();
    }
    __syncthreads();

    __shared__ int s_last;
    if (threadIdx.x == 0) {
        int t = atomicAdd(&g_ticket, 1);
        s_last = (t == (int)(gridDim.x * gridDim.y) - 1);
    }
    __syncthreads();
    if (!s_last) return;

    // ---- finalize ----
    __shared__ float f_c[NB], f_r[NB], f_l[NB];
    {
        int wi = threadIdx.x >> 5;
        int ln = threadIdx.x & 31;
        if (wi < NB) {
            float cs = 0.f, rs = 0.f; int np = 0;
#pragma unroll
            for (int k = 0; k < BLOCKS_X / 32; k++) {
                int p = wi * BLOCKS_X + k * 32 + ln;
                cs += g_part_cls[p];
                rs += g_part_reg[p];
                np += g_part_np[p];
            }
            float lsum = (ln < P2X) ? g_part_loc[wi * P2X + ln] : 0.f;
            cs = warp_sum_f(cs); rs = warp_sum_f(rs);
            lsum = warp_sum_f(lsum); np = warp_sum_i(np);
            bool v = (ln < NM) && (ann[((size_t)wi * NM + ln) * 5 + 4] != -1.0f);
            bool has_gt = __ballot_sync(0xffffffffu, v) != 0u;
            if (ln == 0) {
                float fnp = (float)np;
                bool ok = has_gt && (np > 0);
                f_c[wi] = has_gt ? cs / fmaxf(fnp, 1.f)       : 0.f;
                f_r[wi] = ok     ? rs / fmaxf(fnp * 4.f, 1.f) : 0.f;
                f_l[wi] = ok     ? lsum / fmaxf(fnp, 1.f)     : 0.f;
            }
        }
    }
    __syncthreads();
    if (threadIdx.x == 0) {
        float c = 0.f, r = 0.f, l = 0.f;
#pragma unroll
        for (int k = 0; k < NB; k++) { c += f_c[k]; r += f_r[k]; l += f_l[k]; }
        out[0] = c / (float)NB;
        out[1] = r / (float)NB;
        out[2] = l / (float)NB;
        g_ticket = 0;
#pragma unroll
        for (int k = 0; k < NB; k++) { g_poscnt[k] = 0; g_used[k] = 0u; }
    }
}

// ---------------------------------------------------------------------------
extern "C" void kernel_launch(void* const* d_in, const int* in_sizes, int n_in,
                              void* d_out, int out_size) {
    const float* cls = (const float*)d_in[0];
    const float* reg = (const float*)d_in[1];
    const float* loc = (const float*)d_in[2];
    const float* anc = (const float*)d_in[3];
    const float* ann = (const float*)d_in[4];
    float* out = (float*)d_out;

    pass1_kernel<<<dim3(BLOCKS_X, NB), TPB>>>(cls, reg, loc, anc, ann);
    pass2_kernel<<<dim3(P2X, NB), TPB>>>(ann, out);
}

// round 7
// speedup vs baseline: 2.3005x; 1.1215x over previous
#include <cuda_runtime.h>
#include <cstdint>

#define NB 8
#define NA 65536
#define NC 80
#define NM 32
#define IMG_WH 512.0f
#define TPB 256
#define F4R 20                     // float4 per classification row
#define BLOCKS_X (NA / TPB)        // 256 blocks/image
#define P2X 16                     // pass2 x-blocks per image
#define LN2 0.6931471805599453f

// ---------------------------------------------------------------------------
// Scratch
// ---------------------------------------------------------------------------
__device__ float    g_part_cls[NB * BLOCKS_X];
__device__ float    g_part_reg[NB * BLOCKS_X];
__device__ int      g_part_np [NB * BLOCKS_X];
__device__ float    g_part_loc[NB * P2X];
__device__ unsigned g_used[NB];            // atomicOr from pass1; reset in finalize
__device__ int      g_poscnt[NB];          // reset in finalize
__device__ float4   g_pos_an[NB * NA];     // self-contained pos records
__device__ float4   g_pos_rp[NB * NA];
__device__ float    g_pos_lp[NB * NA];
__device__ int      g_ticket = 0;

__device__ __forceinline__ float warp_sum_f(float v) {
#pragma unroll
    for (int o = 16; o > 0; o >>= 1) v += __shfl_down_sync(0xffffffffu, v, o);
    return v;
}
__device__ __forceinline__ int warp_sum_i(int v) {
#pragma unroll
    for (int o = 16; o > 0; o >>= 1) v += __shfl_down_sync(0xffffffffu, v, o);
    return v;
}

// ---------------------------------------------------------------------------
// Kernel 1 (fused): flags, focal cls stream (+label fix), reg loss, pos records.
// ---------------------------------------------------------------------------
__global__ __launch_bounds__(TPB, 6)
void pass1_kernel(const float* __restrict__ cls,
                  const float* __restrict__ reg,
                  const float* __restrict__ loc,
                  const float* __restrict__ anc,
                  const float* __restrict__ ann) {
    const int b = blockIdx.y;
    const int i = blockIdx.x * TPB + threadIdx.x;   // global anchor

    __shared__ float4   sbox[NM];
    __shared__ float    slbl[NM];
    __shared__ float    sarea_eff[NM];     // 1e30 for invalid boxes
    __shared__ float    sw0[TPB];          // per-anchor cls weight: 0.75 or 0
    __shared__ unsigned s_used;
    __shared__ float    sc[TPB / 32], sr[TPB / 32];
    __shared__ int      sn[TPB / 32];

    if (threadIdx.x < NM) {
        const float* a5 = ann + ((size_t)b * NM + threadIdx.x) * 5;
        float4 bx = make_float4(a5[0], a5[1], a5[2], a5[3]);
        float lbl = a5[4];
        sbox[threadIdx.x] = bx;
        slbl[threadIdx.x] = lbl;
        sarea_eff[threadIdx.x] = (lbl == -1.0f) ? 1e30f
                               : (bx.z - bx.x) * (bx.w - bx.y);
    }
    if (threadIdx.x == 0) s_used = 0u;
    __syncthreads();

    const float4 an = __ldg(((const float4*)anc) + i);
    const float aw = an.z - an.x;
    const float ah = an.w - an.y;
    const float area_a = aw * ah;

    // ---- Phase A: pos/neg, division-free ----
    float maxPos = -1e30f;
    float maxNeg = -1e30f;
#pragma unroll 8
    for (int m = 0; m < NM; m++) {
        float4 bx = sbox[m];
        float iw = fmaxf(fminf(an.z, bx.z) - fmaxf(an.x, bx.x), 0.f);
        float ih = fmaxf(fminf(an.w, bx.w) - fmaxf(an.y, bx.y), 0.f);
        float inter = iw * ih;
        float sab = area_a + sarea_eff[m];
        maxPos = fmaxf(maxPos, fmaf(3.0f, inter, -sab));
        maxNeg = fmaxf(maxNeg, fmaf(3.5f, inter, -sab));
    }
    const bool pos = maxPos >= 0.f;
    const bool neg = maxNeg < 0.f;

    float reg_acc = 0.f;
    float cls_fix = 0.f;

    if (pos) {
        // ---- Phase B: first-max argmax (rare), division-free ----
        float bi = -1.f, bd = 1.f;
        int arg = 0;
#pragma unroll 1
        for (int m = 0; m < NM; m++) {
            float4 bx = sbox[m];
            float iw = fmaxf(fminf(an.z, bx.z) - fmaxf(an.x, bx.x), 0.f);
            float ih = fmaxf(fminf(an.w, bx.w) - fmaxf(an.y, bx.y), 0.f);
            float inter = iw * ih;
            float area_b = (bx.z - bx.x) * (bx.w - bx.y);
            float den = area_a + area_b - inter;
            bool invalid = (slbl[m] == -1.0f);
            float im = invalid ? -1.f : inter;
            float dm = invalid ?  1.f : den;
            if (im * bd > bi * dm) { bi = im; bd = dm; arg = m; }
        }
        const int lbl = (int)slbl[arg];

        // cls label-class fix
        {
            float p = __ldg(cls + ((size_t)b * NA + i) * NC + lbl);
            p = fminf(fmaxf(p, 1e-4f), 1.f - 1e-4f);
            float q = 1.f - p;
            cls_fix = 0.25f * q * q * (-__logf(p)) - 0.75f * p * p * (-__logf(q));
        }

        // self-contained pos record
        float4 rp = __ldg(((const float4*)reg) + (size_t)b * NA + i);
        {
            int slot = atomicAdd(&g_poscnt[b], 1);
            size_t s = (size_t)b * NA + slot;
            g_pos_an[s] = an;
            g_pos_rp[s] = rp;
            g_pos_lp[s] = __ldg(loc + (size_t)b * NA + i);
        }

        // reg loss (bounded denominators: aw,ah >= 8)
        float4 bx = sbox[arg];
        float gwr = bx.z - bx.x;
        float ghr = bx.w - bx.y;
        float gcx = bx.x + 0.5f * gwr;
        float gcy = bx.y + 0.5f * ghr;
        float gw = fmaxf(gwr, 1.f);
        float gh = fmaxf(ghr, 1.f);
        float acx = an.x + 0.5f * aw;
        float acy = an.y + 0.5f * ah;
        float t0 = __fdividef(gcx - acx, aw) * 10.f;
        float t1 = __fdividef(gcy - acy, ah) * 10.f;
        float t2 = __logf(__fdividef(gw, aw)) * 5.f;
        float t3 = __logf(__fdividef(gh, ah)) * 5.f;
        float d0 = fabsf(t0 - rp.x);
        float d1 = fabsf(t1 - rp.y);
        float d2 = fabsf(t2 - rp.z);
        float d3 = fabsf(t3 - rp.w);
        const float th = 1.0f / 9.0f;
        reg_acc += (d0 <= th) ? 4.5f * d0 * d0 : d0 - 0.5f / 9.0f;
        reg_acc += (d1 <= th) ? 4.5f * d1 * d1 : d1 - 0.5f / 9.0f;
        reg_acc += (d2 <= th) ? 4.5f * d2 * d2 : d2 - 0.5f / 9.0f;
        reg_acc += (d3 <= th) ? 4.5f * d3 * d3 : d3 - 0.5f / 9.0f;
        atomicOr(&s_used, 1u << arg);
    }

    sw0[threadIdx.x] = (!pos && !neg) ? 0.f : 0.75f;
    __syncthreads();

    if (threadIdx.x == 0 && s_used) atomicOr(&g_used[b], s_used);

    // ---- Phase C: coalesced branch-free focal stream (5 ops/elt) ----
    // q = max(1-p, 1e-4) preserves the upper clamp exactly; lower clamp on p
    // dropped (term ~1e-8 there, far below tolerance).
    const float4* rowbase =
        (const float4*)(cls + ((size_t)b * NA + (size_t)blockIdx.x * TPB) * NC);

    float cls_acc = 0.f;   // log2 units
#pragma unroll 5
    for (int it = 0; it < F4R; it++) {
        int f4i = it * TPB + threadIdx.x;
        int la  = f4i / F4R;
        float w0 = sw0[la];
        float4 v = __ldg(rowbase + f4i);
        float s4;
        {
            float q = fmaxf(1.f - v.x, 1e-4f);
            s4 = v.x * v.x * __log2f(q);
        }
        {
            float q = fmaxf(1.f - v.y, 1e-4f);
            s4 = fmaf(v.y * v.y, __log2f(q), s4);
        }
        {
            float q = fmaxf(1.f - v.z, 1e-4f);
            s4 = fmaf(v.z * v.z, __log2f(q), s4);
        }
        {
            float q = fmaxf(1.f - v.w, 1e-4f);
            s4 = fmaf(v.w * v.w, __log2f(q), s4);
        }
        cls_acc = fmaf(w0, s4, cls_acc);
    }
    cls_acc = fmaf(cls_acc, -LN2, cls_fix);

    // ---- block reduction ----
    float wc = warp_sum_f(cls_acc);
    float wr = warp_sum_f(reg_acc);
    int   wn = warp_sum_i(pos ? 1 : 0);
    int w = threadIdx.x >> 5, lane = threadIdx.x & 31;
    if (lane == 0) { sc[w] = wc; sr[w] = wr; sn[w] = wn; }
    __syncthreads();
    if (threadIdx.x == 0) {
        float tc = 0.f, tr = 0.f; int tn = 0;
#pragma unroll
        for (int k = 0; k < TPB / 32; k++) { tc += sc[k]; tr += sr[k]; tn += sn[k]; }
        int pidx = b * BLOCKS_X + blockIdx.x;
        g_part_cls[pidx] = tc;
        g_part_reg[pidx] = tr;
        g_part_np [pidx] = tn;
    }
}

// ---------------------------------------------------------------------------
// Kernel 2: loc loss over pos records (division-free max) + ticket finalize.
// ---------------------------------------------------------------------------
__global__ __launch_bounds__(TPB)
void pass2_kernel(const float* __restrict__ ann, float* __restrict__ out) {
    const int b = blockIdx.y;
    const int n = g_poscnt[b];

    __shared__ float4   sbox[NM];
    __shared__ float    sarea[NM];
    __shared__ unsigned s_mask;
    __shared__ float    sl[TPB / 32];

    if (threadIdx.x < 32) {
        bool valid = false;
        if (threadIdx.x < NM) {
            const float* a5 = ann + ((size_t)b * NM + threadIdx.x) * 5;
            float4 bx = make_float4(a5[0], a5[1], a5[2], a5[3]);
            sbox[threadIdx.x]  = bx;
            sarea[threadIdx.x] = (bx.z - bx.x) * (bx.w - bx.y);
            valid = (a5[4] != -1.0f);
        }
        unsigned vm = __ballot_sync(0xffffffffu, valid);
        if (threadIdx.x == 0) s_mask = vm & g_used[b];
    }
    __syncthreads();
    const unsigned mask = s_mask;

    float loc_acc = 0.f;
    for (int j = blockIdx.x * TPB + threadIdx.x; j < n; j += P2X * TPB) {
        size_t s = (size_t)b * NA + j;
        float4 an = g_pos_an[s];
        float4 rp = g_pos_rp[s];
        float  lp = g_pos_lp[s];
        float aw = an.z - an.x;
        float ah = an.w - an.y;
        float acx = an.x + 0.5f * aw;
        float acy = an.y + 0.5f * ah;
        float pcx = acx + rp.x * 0.1f * aw, pcy = acy + rp.y * 0.1f * ah;
        float pw = __expf(rp.z * 0.2f) * aw, ph = __expf(rp.w * 0.2f) * ah;
        float sx1 = fminf(fmaxf(pcx - 0.5f * pw, 0.f), IMG_WH);
        float sy1 = fminf(fmaxf(pcy - 0.5f * ph, 0.f), IMG_WH);
        float sx2 = fminf(fmaxf(pcx + 0.5f * pw, 0.f), IMG_WH);
        float sy2 = fminf(fmaxf(pcy + 0.5f * ph, 0.f), IMG_WH);
        float area_s = (sx2 - sx1) * (sy2 - sy1);

        // division-free max of IoU fractions; unused boxes act like -1 (<=0,
        // clips identically to the reference's -1e9 fill)
        float bi = -1e9f, bd = 1.f;
#pragma unroll 1
        for (int m = 0; m < NM; m++) {
            float4 bx = sbox[m];
            float iw = fmaxf(fminf(sx2, bx.z) - fmaxf(sx1, bx.x), 0.f);
            float ih = fmaxf(fminf(sy2, bx.w) - fmaxf(sy1, bx.y), 0.f);
            float inter = iw * ih;
            float den = fmaxf(area_s + sarea[m] - inter, 1e-8f);
            bool used = (mask >> m) & 1u;
            float im = used ? inter : -1.f;
            float dm = used ? den   :  1.f;
            if (im * bd > bi * dm) { bi = im; bd = dm; }
        }
        float best = __fdividef(bi, bd);
        float ls = fminf(fmaxf(1.f - fabsf(lp - best), 1e-4f), 1.f - 1e-4f);
        loc_acc += -__logf(ls);
    }

    float wl = warp_sum_f(loc_acc);
    int w = threadIdx.x >> 5, lane = threadIdx.x & 31;
    if (lane == 0) sl[w] = wl;
    __syncthreads();
    if (threadIdx.x == 0) {
        float tl = 0.f;
#pragma unroll
        for (int k = 0; k < TPB / 32; k++) tl += sl[k];
        g_part_loc[b * P2X + blockIdx.x] = tl;
        __threadfence();
    }
    __syncthreads();

    __shared__ int s_last;
    if (threadIdx.x == 0) {
        int t = atomicAdd(&g_ticket, 1);
        s_last = (t == (int)(gridDim.x * gridDim.y) - 1);
    }
    __syncthreads();
    if (!s_last) return;

    // ---- finalize ----
    __shared__ float f_c[NB], f_r[NB], f_l[NB];
    {
        int wi = threadIdx.x >> 5;
        int ln = threadIdx.x & 31;
        if (wi < NB) {
            float cs = 0.f, rs = 0.f; int np = 0;
#pragma unroll
            for (int k = 0; k < BLOCKS_X / 32; k++) {
                int p = wi * BLOCKS_X + k * 32 + ln;
                cs += g_part_cls[p];
                rs += g_part_reg[p];
                np += g_part_np[p];
            }
            float lsum = (ln < P2X) ? g_part_loc[wi * P2X + ln] : 0.f;
            cs = warp_sum_f(cs); rs = warp_sum_f(rs);
            lsum = warp_sum_f(lsum); np = warp_sum_i(np);
            bool v = (ln < NM) && (ann[((size_t)wi * NM + ln) * 5 + 4] != -1.0f);
            bool has_gt = __ballot_sync(0xffffffffu, v) != 0u;
            if (ln == 0) {
                float fnp = (float)np;
                bool ok = has_gt && (np > 0);
                f_c[wi] = has_gt ? cs / fmaxf(fnp, 1.f)       : 0.f;
                f_r[wi] = ok     ? rs / fmaxf(fnp * 4.f, 1.f) : 0.f;
                f_l[wi] = ok     ? lsum / fmaxf(fnp, 1.f)     : 0.f;
            }
        }
    }
    __syncthreads();
    if (threadIdx.x == 0) {
        float c = 0.f, r = 0.f, l = 0.f;
#pragma unroll
        for (int k = 0; k < NB; k++) { c += f_c[k]; r += f_r[k]; l += f_l[k]; }
        out[0] = c / (float)NB;
        out[1] = r / (float)NB;
        out[2] = l / (float)NB;
        g_ticket = 0;
#pragma unroll
        for (int k = 0; k < NB; k++) { g_poscnt[k] = 0; g_used[k] = 0u; }
    }
}

// ---------------------------------------------------------------------------
extern "C" void kernel_launch(void* const* d_in, const int* in_sizes, int n_in,
                              void* d_out, int out_size) {
    const float* cls = (const float*)d_in[0];
    const float* reg = (const float*)d_in[1];
    const float* loc = (const float*)d_in[2];
    const float* anc = (const float*)d_in[3];
    const float* ann = (const float*)d_in[4];
    float* out = (float*)d_out;

    pass1_kernel<<<dim3(BLOCKS_X, NB), TPB>>>(cls, reg, loc, anc, ann);
    pass2_kernel<<<dim3(P2X, NB), TPB>>>(ann, out);
}